// round 12
// baseline (speedup 1.0000x reference)
#include <cuda_runtime.h>
#include <cuda_bf16.h>
#include <math.h>

// ---------------- problem constants ----------------
#define F_DIM 128
#define IN_DIM 129          // F_DIM + 1 (binary feature)
#define H_DIM 64
#define NEG_SLOPE 0.2f
#define N_MAX 50000
#define E_MAX 800000

// ---------------- scratch (no allocations allowed) ----------------
__device__ __align__(16) float g_xl[N_MAX * H_DIM];
__device__ __align__(16) float g_xr[N_MAX * H_DIM];
__device__ __align__(16) float g_h [N_MAX * H_DIM];
__device__ int   g_deg[N_MAX];
__device__ int   g_rowptr[N_MAX + 1];
__device__ int   g_cursor[N_MAX];
__device__ int   g_adj[E_MAX];
__device__ __align__(16) int g_eidx[2 * E_MAX];
__device__ int   g_is64;
__device__ int   g_bsum[64];
__device__ int   g_boff[64];

// ============================================================
// 0) Edge dtype detection + conversion.
// ============================================================
__global__ void detect_kernel(const int* __restrict__ w, int nwords) {
    if (threadIdx.x == 0 && blockIdx.x == 0) {
        int is64 = 1;
        for (int i = 0; i < 64; i++) {
            int idx = 2 * i + 1;
            if (idx >= nwords) break;
            if (w[idx] != 0) { is64 = 0; break; }
        }
        g_is64 = is64;
    }
}

__global__ void convert_kernel(const void* __restrict__ ei, int total) {
    int e = blockIdx.x * blockDim.x + threadIdx.x;
    if (e < total) {
        g_eidx[e] = g_is64 ? (int)((const long long*)ei)[e]
                           : ((const int*)ei)[e];
    }
}

// ============================================================
// 1) Input projection GEMM: x[N,129] @ [Wl;Wr]^T -> xl[N,64], xr[N,64]
//    Block tile 128 nodes x 128 outputs, thread tile 8x8:
//    16 LDS per 64 FFMA (2x better intensity than R3's 12/32).
//    smem 129KB (1 CTA/SM, 8 warps), stride 129, conflict-free,
//    scalar staging (proven safe).
// ============================================================
#define PROJ_SMEM ((128 + 128) * IN_DIM * 4)

__global__ __launch_bounds__(256) void proj_kernel(
        const float* __restrict__ xf,
        const float* __restrict__ xb,
        const float* __restrict__ Wl,
        const float* __restrict__ bl,
        const float* __restrict__ Wr,
        const float* __restrict__ br,
        int N) {
    extern __shared__ float sm[];
    float* Ws = sm;                  // [128][129]  rows 0..63 = Wl, 64..127 = Wr
    float* xs = sm + 128 * IN_DIM;   // [128][129]

    const int tid = threadIdx.x;
    const int n0 = blockIdx.x * 128;

    for (int i = tid; i < 64 * IN_DIM; i += 256) Ws[i] = Wl[i];
    for (int i = tid; i < 64 * IN_DIM; i += 256) Ws[64 * IN_DIM + i] = Wr[i];
    for (int i = tid; i < 128 * IN_DIM; i += 256) {
        int n = i / IN_DIM, k = i - n * IN_DIM;
        int node = n0 + n;
        float v = 0.f;
        if (node < N) v = (k < F_DIM) ? xf[(size_t)node * F_DIM + k] : xb[node];
        xs[i] = v;
    }
    __syncthreads();

    const int tn = tid & 15;   // output group (h = tn + 16*j, j=0..7)
    const int tm = tid >> 4;   // node group   (n = tm + 16*i, i=0..7)

    float acc[8][8];
#pragma unroll
    for (int i = 0; i < 8; i++)
#pragma unroll
        for (int j = 0; j < 8; j++) acc[i][j] = 0.f;

    const float* xbase = xs + tm * IN_DIM;
    const float* wbase = Ws + tn * IN_DIM;

    float xv0[8], wv0[8], xv1[8], wv1[8];

#define LOADX(buf, kk)                                        \
    {                                                         \
        _Pragma("unroll")                                     \
        for (int i = 0; i < 8; i++)                           \
            buf[i] = xbase[i * 16 * IN_DIM + (kk)];           \
    }
#define LOADW(buf, kk)                                        \
    {                                                         \
        _Pragma("unroll")                                     \
        for (int j = 0; j < 8; j++)                           \
            buf[j] = wbase[j * 16 * IN_DIM + (kk)];           \
    }
#define FFMAS(xb_, wb_)                                       \
    {                                                         \
        _Pragma("unroll")                                     \
        for (int i = 0; i < 8; i++)                           \
            _Pragma("unroll")                                 \
            for (int j = 0; j < 8; j++)                       \
                acc[i][j] = fmaf(xb_[i], wb_[j], acc[i][j]);  \
    }

    LOADX(xv0, 0);
    LOADW(wv0, 0);
#pragma unroll 2
    for (int k = 0; k + 2 < IN_DIM; k += 2) {
        LOADX(xv1, k + 1);
        LOADW(wv1, k + 1);
        FFMAS(xv0, wv0);
        LOADX(xv0, k + 2);
        LOADW(wv0, k + 2);
        FFMAS(xv1, wv1);
    }
    // epilogue: K=129 odd — loop exits at k=128, buf0 holds k=128
    FFMAS(xv0, wv0);

#undef LOADX
#undef LOADW
#undef FFMAS

#pragma unroll
    for (int i = 0; i < 8; i++) {
        int node = n0 + tm + 16 * i;
        if (node >= N) continue;
#pragma unroll
        for (int j = 0; j < 8; j++) {
            int h = tn + 16 * j;
            if (h < H_DIM) {
                g_xl[(size_t)node * H_DIM + h] = acc[i][j] + bl[h];
            } else {
                g_xr[(size_t)node * H_DIM + (h - H_DIM)] = acc[i][j] + br[h - H_DIM];
            }
        }
    }
}

// ============================================================
// 2) CSR build
// ============================================================
__global__ void zero_deg_kernel(int N) {
    int i = blockIdx.x * blockDim.x + threadIdx.x;
    if (i < N) g_deg[i] = 0;
}

__global__ void hist_kernel(int E, int N) {
    int e = blockIdx.x * blockDim.x + threadIdx.x;
    if (e < E) {
        int d = g_eidx[E + e];   // dst
        if ((unsigned)d < (unsigned)N) atomicAdd(&g_deg[d], 1);
    }
}

__global__ void scan_block_kernel(int N) {
    __shared__ int s[1024];
    const int b = blockIdx.x, t = threadIdx.x;
    const int idx = b * 1024 + t;
    int v = (idx < N) ? g_deg[idx] : 0;
    s[t] = v;
    __syncthreads();
    for (int off = 1; off < 1024; off <<= 1) {
        int x = (t >= off) ? s[t - off] : 0;
        __syncthreads();
        s[t] += x;
        __syncthreads();
    }
    if (idx < N) g_rowptr[idx + 1] = s[t];
    if (t == 1023) g_bsum[b] = s[1023];
}

__global__ void scan_tops_kernel(int NB) {
    __shared__ int s[64];
    const int t = threadIdx.x;
    int v = (t < NB) ? g_bsum[t] : 0;
    s[t] = v;
    __syncthreads();
    for (int off = 1; off < 64; off <<= 1) {
        int x = (t >= off) ? s[t - off] : 0;
        __syncthreads();
        s[t] += x;
        __syncthreads();
    }
    if (t < NB) g_boff[t] = s[t] - v;
}

__global__ void scan_fix_kernel(int N) {
    int i = blockIdx.x * blockDim.x + threadIdx.x;
    if (i < N) {
        int r = g_rowptr[i + 1] + g_boff[i >> 10];
        g_rowptr[i + 1] = r;
        g_cursor[i] = r - g_deg[i];
    }
    if (i == 0) g_rowptr[0] = 0;
}

__global__ void scatter_kernel(int E, int N) {
    int e = blockIdx.x * blockDim.x + threadIdx.x;
    if (e < E) {
        int s = g_eidx[e];
        int d = g_eidx[E + e];
        if ((unsigned)d < (unsigned)N && (unsigned)s < (unsigned)N) {
            int pos = atomicAdd(&g_cursor[d], 1);
            if (pos < E_MAX) g_adj[pos] = s;
        }
    }
}

// ============================================================
// 3) Per-node GATv2 attention + aggregation (VERBATIM from R9).
// ============================================================
__global__ void agg_kernel(const float* __restrict__ att,
                           const float* __restrict__ gbias, int N) {
    const int warp = (blockIdx.x * blockDim.x + threadIdx.x) >> 5;
    const int lane = threadIdx.x & 31;
    if (warp >= N) return;
    const int i = warp;
    const unsigned FULL = 0xffffffffu;

    const float2 xri = *(const float2*)(g_xr + (size_t)i * H_DIM + lane * 2);
    float2 a;  a.x = att[lane * 2];  a.y = att[lane * 2 + 1];
    const float2 xli = *(const float2*)(g_xl + (size_t)i * H_DIM + lane * 2);

    auto partial = [&](float2 xlj) -> float {
        float v0 = xlj.x + xri.x;
        float v1 = xlj.y + xri.y;
        v0 = (v0 > 0.f) ? v0 : NEG_SLOPE * v0;
        v1 = (v1 > 0.f) ? v1 : NEG_SLOPE * v1;
        return fmaf(v0, a.x, v1 * a.y);
    };

    float m;
    {
        float p = partial(xli);
#pragma unroll
        for (int off = 16; off > 0; off >>= 1)
            p += __shfl_xor_sync(FULL, p, off);
        m = p;
    }
    float d = 1.f;
    float2 acc = xli;

    auto update = [&](float sc, float2 xlj) {
        if (sc <= m) {
            float w = __expf(sc - m);
            d += w;
            acc.x = fmaf(w, xlj.x, acc.x);
            acc.y = fmaf(w, xlj.y, acc.y);
        } else {
            float scale = __expf(m - sc);
            d = fmaf(d, scale, 1.f);
            acc.x = fmaf(acc.x, scale, xlj.x);
            acc.y = fmaf(acc.y, scale, xlj.y);
            m = sc;
        }
    };

    const int s = g_rowptr[i], e = g_rowptr[i + 1];
    for (int b = s; b < e; b += 32) {
        int myj = (b + lane < e) ? g_adj[b + lane] : 0;
        int cnt = min(32, e - b);
        int k = 0;
        for (; k + 1 < cnt; k += 2) {
            int j0 = __shfl_sync(FULL, myj, k);
            int j1 = __shfl_sync(FULL, myj, k + 1);
            float2 x0 = *(const float2*)(g_xl + (size_t)j0 * H_DIM + lane * 2);
            float2 x1 = *(const float2*)(g_xl + (size_t)j1 * H_DIM + lane * 2);
            float p0 = partial(x0);
            float p1 = partial(x1);
#pragma unroll
            for (int off = 16; off > 0; off >>= 1) {
                p0 += __shfl_xor_sync(FULL, p0, off);
                p1 += __shfl_xor_sync(FULL, p1, off);
            }
            update(p0, x0);
            update(p1, x1);
        }
        if (k < cnt) {
            int j0 = __shfl_sync(FULL, myj, k);
            float2 x0 = *(const float2*)(g_xl + (size_t)j0 * H_DIM + lane * 2);
            float p0 = partial(x0);
#pragma unroll
            for (int off = 16; off > 0; off >>= 1)
                p0 += __shfl_xor_sync(FULL, p0, off);
            update(p0, x0);
        }
    }

    const float inv = 1.f / d;
    float gb0 = gbias[lane * 2], gb1 = gbias[lane * 2 + 1];
    float o0 = fmaf(acc.x, inv, gb0);
    float o1 = fmaf(acc.y, inv, gb1);
    o0 = (o0 > 0.f) ? o0 : (__expf(o0) - 1.f);
    o1 = (o1 > 0.f) ? o1 : (__expf(o1) - 1.f);
    float2 r; r.x = o0; r.y = o1;
    *(float2*)(g_h + (size_t)i * H_DIM + lane * 2) = r;
}

// ============================================================
// 4) Output GEMM (VERBATIM from the passing R3/R9 kernel).
// ============================================================
__global__ void outgemm_kernel(const float* __restrict__ Wo,
                               const float* __restrict__ bo,
                               float* __restrict__ out, int N) {
    __shared__ float Ws[128 * 65];   // padded stride 65 (odd)
    __shared__ float hs[32 * 65];

    const int tid = threadIdx.x;
    const int n0 = blockIdx.x * 32;

    for (int i = tid; i < 128 * 64; i += 256) {
        int f = i >> 6, k = i & 63;
        Ws[f * 65 + k] = Wo[i];
    }
    for (int i = tid; i < 32 * 64; i += 256) {
        int n = i >> 6, k = i & 63;
        int node = n0 + n;
        hs[n * 65 + k] = (node < N) ? g_h[(size_t)node * H_DIM + k] : 0.f;
    }
    __syncthreads();

    const int tn = tid & 15;   // f = tn + 16*j
    const int tm = tid >> 4;   // n = tm + 16*i

    float acc[2][8];
#pragma unroll
    for (int i = 0; i < 2; i++)
#pragma unroll
        for (int j = 0; j < 8; j++) acc[i][j] = 0.f;

#pragma unroll 4
    for (int k = 0; k < H_DIM; k++) {
        float xv[2], wv[8];
#pragma unroll
        for (int i = 0; i < 2; i++) xv[i] = hs[(tm + 16 * i) * 65 + k];
#pragma unroll
        for (int j = 0; j < 8; j++) wv[j] = Ws[(tn + 16 * j) * 65 + k];
#pragma unroll
        for (int i = 0; i < 2; i++)
#pragma unroll
            for (int j = 0; j < 8; j++) acc[i][j] = fmaf(xv[i], wv[j], acc[i][j]);
    }

#pragma unroll
    for (int i = 0; i < 2; i++) {
        int node = n0 + tm + 16 * i;
        if (node >= N) continue;
#pragma unroll
        for (int j = 0; j < 8; j++) {
            int f = tn + 16 * j;
            out[(size_t)node * F_DIM + f] = acc[i][j] + bo[f];
        }
    }
}

// ============================================================
// 5) dispersion tail: softplus
// ============================================================
__global__ void disp_kernel(const float* __restrict__ disp, float* __restrict__ out) {
    int t = threadIdx.x;
    if (t < F_DIM) {
        float x = disp[t];
        out[t] = fmaxf(x, 0.f) + log1pf(__expf(-fabsf(x)));
    }
}

// ============================================================
extern "C" void kernel_launch(void* const* d_in, const int* in_sizes, int n_in,
                              void* d_out, int out_size) {
    const float*     xf   = (const float*)d_in[0];
    const float*     xb   = (const float*)d_in[1];
    const void*      ei   = d_in[2];
    const float*     Wl   = (const float*)d_in[3];
    const float*     bl   = (const float*)d_in[4];
    const float*     Wr   = (const float*)d_in[5];
    const float*     br   = (const float*)d_in[6];
    const float*     att  = (const float*)d_in[7];
    const float*     gb   = (const float*)d_in[8];
    const float*     Wo   = (const float*)d_in[9];
    const float*     bo   = (const float*)d_in[10];
    const float*     disp = (const float*)d_in[11];

    const int N = in_sizes[0] / F_DIM;
    const int E = in_sizes[2] / 2;
    const int NB = (N + 1023) / 1024;
    float* out = (float*)d_out;

    cudaFuncSetAttribute(proj_kernel,
                         cudaFuncAttributeMaxDynamicSharedMemorySize, PROJ_SMEM);

    detect_kernel<<<1, 32>>>((const int*)ei, 2 * E);
    convert_kernel<<<(2 * E + 255) / 256, 256>>>(ei, 2 * E);
    zero_deg_kernel<<<(N + 255) / 256, 256>>>(N);
    proj_kernel<<<(N + 127) / 128, 256, PROJ_SMEM>>>(xf, xb, Wl, bl, Wr, br, N);
    hist_kernel<<<(E + 255) / 256, 256>>>(E, N);
    scan_block_kernel<<<NB, 1024>>>(N);
    scan_tops_kernel<<<1, 64>>>(NB);
    scan_fix_kernel<<<(N + 255) / 256, 256>>>(N);
    scatter_kernel<<<(E + 255) / 256, 256>>>(E, N);
    agg_kernel<<<(N + 7) / 8, 256>>>(att, gb, N);
    outgemm_kernel<<<(N + 31) / 32, 256>>>(Wo, bo, out, N);
    disp_kernel<<<1, 128>>>(disp, out + (size_t)N * F_DIM);
}

// round 13
// speedup vs baseline: 1.6114x; 1.6114x over previous
#include <cuda_runtime.h>
#include <cuda_bf16.h>
#include <math.h>
#include <stdint.h>

// ---------------- problem constants ----------------
#define F_DIM 128
#define IN_DIM 129          // F_DIM + 1 (binary feature)
#define H_DIM 64
#define NEG_SLOPE 0.2f
#define N_MAX 50000
#define E_MAX 800000
#define KPAD 136            // padded K for bf16 tiles (272B rows: ldmatrix conflict-free)

// ---------------- scratch (no allocations allowed) ----------------
__device__ __align__(16) float g_xl[N_MAX * H_DIM];
__device__ __align__(16) float g_xr[N_MAX * H_DIM];
__device__ __align__(16) float g_h [N_MAX * H_DIM];
__device__ int   g_deg[N_MAX];
__device__ int   g_rowptr[N_MAX + 1];
__device__ int   g_cursor[N_MAX];
__device__ int   g_adj[E_MAX];
__device__ __align__(16) int g_eidx[2 * E_MAX];
__device__ int   g_is64;
__device__ int   g_bsum[64];
__device__ int   g_boff[64];
// bf16-split weights for the MMA projection
__device__ __align__(16) __nv_bfloat16 g_w_hi[128 * KPAD];
__device__ __align__(16) __nv_bfloat16 g_w_lo[128 * KPAD];
__device__ __align__(16) float g_wb[128];     // W[:,128] (binary-feature column)
__device__ __align__(16) float g_wbias[128];  // [bl; br]

// ============================================================
// PTX helpers
// ============================================================
__device__ __forceinline__ uint32_t smem_u32(const void* p) {
    uint32_t a;
    asm("{ .reg .u64 t; cvta.to.shared.u64 t, %1; cvt.u32.u64 %0, t; }"
        : "=r"(a) : "l"(p));
    return a;
}

__device__ __forceinline__ void ldsm_x4(uint32_t& r0, uint32_t& r1,
                                        uint32_t& r2, uint32_t& r3, uint32_t addr) {
    asm volatile("ldmatrix.sync.aligned.m8n8.x4.shared.b16 {%0,%1,%2,%3}, [%4];"
                 : "=r"(r0), "=r"(r1), "=r"(r2), "=r"(r3) : "r"(addr));
}

__device__ __forceinline__ void mma16816(float& d0, float& d1, float& d2, float& d3,
                                         uint32_t a0, uint32_t a1, uint32_t a2, uint32_t a3,
                                         uint32_t b0, uint32_t b1) {
    asm volatile(
        "mma.sync.aligned.m16n8k16.row.col.f32.bf16.bf16.f32 "
        "{%0,%1,%2,%3},{%4,%5,%6,%7},{%8,%9},{%0,%1,%2,%3};"
        : "+f"(d0), "+f"(d1), "+f"(d2), "+f"(d3)
        : "r"(a0), "r"(a1), "r"(a2), "r"(a3), "r"(b0), "r"(b1));
}

// ============================================================
// 0) Edge dtype detection + conversion.
// ============================================================
__global__ void detect_kernel(const int* __restrict__ w, int nwords) {
    if (threadIdx.x == 0 && blockIdx.x == 0) {
        int is64 = 1;
        for (int i = 0; i < 64; i++) {
            int idx = 2 * i + 1;
            if (idx >= nwords) break;
            if (w[idx] != 0) { is64 = 0; break; }
        }
        g_is64 = is64;
    }
}

__global__ void convert_kernel(const void* __restrict__ ei, int total) {
    int e = blockIdx.x * blockDim.x + threadIdx.x;
    if (e < total) {
        g_eidx[e] = g_is64 ? (int)((const long long*)ei)[e]
                           : ((const int*)ei)[e];
    }
}

// ============================================================
// 0b) Weight split: [Wl;Wr] fp32 -> hi/lo bf16 in padded [128][KPAD]
//     layout, plus f32 binary-column and bias arrays.
// ============================================================
__global__ void wconv_kernel(const float* __restrict__ Wl,
                             const float* __restrict__ Wr,
                             const float* __restrict__ bl,
                             const float* __restrict__ br) {
    int idx = blockIdx.x * blockDim.x + threadIdx.x;
    if (idx < 128 * KPAD) {
        int h = idx / KPAD, kp = idx - h * KPAD;
        float v = 0.f;
        if (kp < 128) v = (h < 64) ? Wl[h * IN_DIM + kp] : Wr[(h - 64) * IN_DIM + kp];
        __nv_bfloat16 hi = __float2bfloat16(v);
        g_w_hi[idx] = hi;
        g_w_lo[idx] = __float2bfloat16(v - __bfloat162float(hi));
    }
    if (idx < 128) {
        g_wb[idx]    = (idx < 64) ? Wl[idx * IN_DIM + 128] : Wr[(idx - 64) * IN_DIM + 128];
        g_wbias[idx] = (idx < 64) ? bl[idx] : br[idx - 64];
    }
}

// ============================================================
// 1) Input projection via bf16-split tensor-core MMA.
//    CTA: 64 nodes x 128 outputs, 8 warps, warp tile m16 x n64.
//    D = Ah*Bh + Ah*Bl + Al*Bh (fp32 acc), + xb*W[:,128] + bias.
// ============================================================
#define SM_XH   0
#define SM_XL   17408
#define SM_WH   34816
#define SM_WL   69632
#define SM_XB   104448
#define SM_WB   104704
#define SM_BIAS 105216
#define PROJ2_SMEM 105728

__global__ __launch_bounds__(256) void proj_mma_kernel(
        const float* __restrict__ xf,
        const float* __restrict__ xb,
        int N) {
    extern __shared__ char smx[];
    __nv_bfloat16* xh = (__nv_bfloat16*)(smx + SM_XH);
    __nv_bfloat16* xl = (__nv_bfloat16*)(smx + SM_XL);
    float* xbs = (float*)(smx + SM_XB);
    float* wbs = (float*)(smx + SM_WB);
    float* bis = (float*)(smx + SM_BIAS);

    const int tid = threadIdx.x;
    const int n0 = blockIdx.x * 64;

    // stage W hi/lo (uint4 copies from my 16B-aligned globals)
    {
        const uint4* gwh = (const uint4*)g_w_hi;
        const uint4* gwl = (const uint4*)g_w_lo;
        uint4* swh = (uint4*)(smx + SM_WH);
        uint4* swl = (uint4*)(smx + SM_WL);
        for (int i = tid; i < 2176; i += 256) swh[i] = gwh[i];
        for (int i = tid; i < 2176; i += 256) swl[i] = gwl[i];
    }
    // stage + split x (scalar LDG from d_in, proven safe)
    for (int i = tid; i < 64 * 128; i += 256) {
        int n = i >> 7, k = i & 127;
        int node = n0 + n;
        float v = (node < N) ? xf[(size_t)node * F_DIM + k] : 0.f;
        __nv_bfloat16 hi = __float2bfloat16(v);
        xh[n * KPAD + k] = hi;
        xl[n * KPAD + k] = __float2bfloat16(v - __bfloat162float(hi));
    }
    for (int i = tid; i < 64 * 8; i += 256) {           // zero pad cols 128..135
        int n = i >> 3, k = 128 + (i & 7);
        xh[n * KPAD + k] = __float2bfloat16(0.f);
        xl[n * KPAD + k] = __float2bfloat16(0.f);
    }
    if (tid < 64) {
        int node = n0 + tid;
        xbs[tid] = (node < N) ? xb[node] : 0.f;
    }
    if (tid < 128) { wbs[tid] = g_wb[tid]; bis[tid] = g_wbias[tid]; }
    __syncthreads();

    const int warp = tid >> 5, lane = tid & 31;
    const int mbase = (warp & 3) * 16;    // node rows [mbase, mbase+16)
    const int nwb   = (warp >> 2) * 64;   // output cols [nwb, nwb+64)

    float acc[8][4];
#pragma unroll
    for (int t = 0; t < 8; t++)
#pragma unroll
        for (int q = 0; q < 4; q++) acc[t][q] = 0.f;

    const uint32_t sb = smem_u32(smx);
    const uint32_t xh_a = sb + SM_XH, xl_a = sb + SM_XL;
    const uint32_t wh_a = sb + SM_WH, wl_a = sb + SM_WL;

    const int tr = lane & 7, tg = lane >> 3;
    // A tiles: t0=(m0-7,k0-7) t1=(m8-15,k0-7) t2=(m0-7,k8-15) t3=(m8-15,k8-15)
    const uint32_t aoff =
        ((uint32_t)((mbase + tr + (tg & 1) * 8) * KPAD + ((tg >> 1) * 8))) * 2u;
    // B tiles: t0=(n0-7,k0-7) t1=(n0-7,k8-15) t2=(n8-15,k0-7) t3=(n8-15,k8-15)
    uint32_t boff[4];
#pragma unroll
    for (int ng = 0; ng < 4; ng++)
        boff[ng] = ((uint32_t)((nwb + ng * 16 + tr + (tg >> 1) * 8) * KPAD
                               + ((tg & 1) * 8))) * 2u;

#pragma unroll
    for (int kc = 0; kc < 8; kc++) {
        const uint32_t kb = (uint32_t)kc * 32u;   // 16 bf16 = 32 bytes
        uint32_t ah0, ah1, ah2, ah3, al0, al1, al2, al3;
        ldsm_x4(ah0, ah1, ah2, ah3, xh_a + aoff + kb);
        ldsm_x4(al0, al1, al2, al3, xl_a + aoff + kb);
#pragma unroll
        for (int ng = 0; ng < 4; ng++) {
            uint32_t bh0, bh1, bh2, bh3, bl0_, bl1_, bl2_, bl3_;
            ldsm_x4(bh0, bh1, bh2, bh3, wh_a + boff[ng] + kb);
            ldsm_x4(bl0_, bl1_, bl2_, bl3_, wl_a + boff[ng] + kb);
            float* d0 = acc[ng * 2 + 0];
            float* d1 = acc[ng * 2 + 1];
            mma16816(d0[0], d0[1], d0[2], d0[3], ah0, ah1, ah2, ah3, bh0, bh1);
            mma16816(d1[0], d1[1], d1[2], d1[3], ah0, ah1, ah2, ah3, bh2, bh3);
            mma16816(d0[0], d0[1], d0[2], d0[3], ah0, ah1, ah2, ah3, bl0_, bl1_);
            mma16816(d1[0], d1[1], d1[2], d1[3], ah0, ah1, ah2, ah3, bl2_, bl3_);
            mma16816(d0[0], d0[1], d0[2], d0[3], al0, al1, al2, al3, bh0, bh1);
            mma16816(d1[0], d1[1], d1[2], d1[3], al0, al1, al2, al3, bh2, bh3);
        }
    }

    // epilogue: + xb*W[:,128] + bias, write float2 to g_xl/g_xr
    const int r = lane >> 2;
    const int cq = (lane & 3) * 2;
    const int mr0 = mbase + r, mr1 = mbase + r + 8;
    const int node0 = n0 + mr0, node1 = n0 + mr1;
    const float xb0 = xbs[mr0], xb1 = xbs[mr1];
#pragma unroll
    for (int nt = 0; nt < 8; nt++) {
        int h = nwb + nt * 8 + cq;
        float w0 = wbs[h], w1 = wbs[h + 1];
        float b0 = bis[h], b1 = bis[h + 1];
        float v0 = acc[nt][0] + xb0 * w0 + b0;
        float v1 = acc[nt][1] + xb0 * w1 + b1;
        float v2 = acc[nt][2] + xb1 * w0 + b0;
        float v3 = acc[nt][3] + xb1 * w1 + b1;
        float* base0;
        float* base1;
        if (h < H_DIM) {
            base0 = g_xl + (size_t)node0 * H_DIM + h;
            base1 = g_xl + (size_t)node1 * H_DIM + h;
        } else {
            base0 = g_xr + (size_t)node0 * H_DIM + (h - H_DIM);
            base1 = g_xr + (size_t)node1 * H_DIM + (h - H_DIM);
        }
        if (node0 < N) { float2 p; p.x = v0; p.y = v1; *(float2*)base0 = p; }
        if (node1 < N) { float2 p; p.x = v2; p.y = v3; *(float2*)base1 = p; }
    }
}

// ============================================================
// 2) CSR build
// ============================================================
__global__ void zero_deg_kernel(int N) {
    int i = blockIdx.x * blockDim.x + threadIdx.x;
    if (i < N) g_deg[i] = 0;
}

__global__ void hist_kernel(int E, int N) {
    int e = blockIdx.x * blockDim.x + threadIdx.x;
    if (e < E) {
        int d = g_eidx[E + e];   // dst
        if ((unsigned)d < (unsigned)N) atomicAdd(&g_deg[d], 1);
    }
}

__global__ void scan_block_kernel(int N) {
    __shared__ int s[1024];
    const int b = blockIdx.x, t = threadIdx.x;
    const int idx = b * 1024 + t;
    int v = (idx < N) ? g_deg[idx] : 0;
    s[t] = v;
    __syncthreads();
    for (int off = 1; off < 1024; off <<= 1) {
        int x = (t >= off) ? s[t - off] : 0;
        __syncthreads();
        s[t] += x;
        __syncthreads();
    }
    if (idx < N) g_rowptr[idx + 1] = s[t];
    if (t == 1023) g_bsum[b] = s[1023];
}

__global__ void scan_tops_kernel(int NB) {
    __shared__ int s[64];
    const int t = threadIdx.x;
    int v = (t < NB) ? g_bsum[t] : 0;
    s[t] = v;
    __syncthreads();
    for (int off = 1; off < 64; off <<= 1) {
        int x = (t >= off) ? s[t - off] : 0;
        __syncthreads();
        s[t] += x;
        __syncthreads();
    }
    if (t < NB) g_boff[t] = s[t] - v;
}

__global__ void scan_fix_kernel(int N) {
    int i = blockIdx.x * blockDim.x + threadIdx.x;
    if (i < N) {
        int r = g_rowptr[i + 1] + g_boff[i >> 10];
        g_rowptr[i + 1] = r;
        g_cursor[i] = r - g_deg[i];
    }
    if (i == 0) g_rowptr[0] = 0;
}

__global__ void scatter_kernel(int E, int N) {
    int e = blockIdx.x * blockDim.x + threadIdx.x;
    if (e < E) {
        int s = g_eidx[e];
        int d = g_eidx[E + e];
        if ((unsigned)d < (unsigned)N && (unsigned)s < (unsigned)N) {
            int pos = atomicAdd(&g_cursor[d], 1);
            if (pos < E_MAX) g_adj[pos] = s;
        }
    }
}

// ============================================================
// 3) Per-node GATv2 attention + aggregation (VERBATIM from R9).
// ============================================================
__global__ void agg_kernel(const float* __restrict__ att,
                           const float* __restrict__ gbias, int N) {
    const int warp = (blockIdx.x * blockDim.x + threadIdx.x) >> 5;
    const int lane = threadIdx.x & 31;
    if (warp >= N) return;
    const int i = warp;
    const unsigned FULL = 0xffffffffu;

    const float2 xri = *(const float2*)(g_xr + (size_t)i * H_DIM + lane * 2);
    float2 a;  a.x = att[lane * 2];  a.y = att[lane * 2 + 1];
    const float2 xli = *(const float2*)(g_xl + (size_t)i * H_DIM + lane * 2);

    auto partial = [&](float2 xlj) -> float {
        float v0 = xlj.x + xri.x;
        float v1 = xlj.y + xri.y;
        v0 = (v0 > 0.f) ? v0 : NEG_SLOPE * v0;
        v1 = (v1 > 0.f) ? v1 : NEG_SLOPE * v1;
        return fmaf(v0, a.x, v1 * a.y);
    };

    float m;
    {
        float p = partial(xli);
#pragma unroll
        for (int off = 16; off > 0; off >>= 1)
            p += __shfl_xor_sync(FULL, p, off);
        m = p;
    }
    float d = 1.f;
    float2 acc = xli;

    auto update = [&](float sc, float2 xlj) {
        if (sc <= m) {
            float w = __expf(sc - m);
            d += w;
            acc.x = fmaf(w, xlj.x, acc.x);
            acc.y = fmaf(w, xlj.y, acc.y);
        } else {
            float scale = __expf(m - sc);
            d = fmaf(d, scale, 1.f);
            acc.x = fmaf(acc.x, scale, xlj.x);
            acc.y = fmaf(acc.y, scale, xlj.y);
            m = sc;
        }
    };

    const int s = g_rowptr[i], e = g_rowptr[i + 1];
    for (int b = s; b < e; b += 32) {
        int myj = (b + lane < e) ? g_adj[b + lane] : 0;
        int cnt = min(32, e - b);
        int k = 0;
        for (; k + 1 < cnt; k += 2) {
            int j0 = __shfl_sync(FULL, myj, k);
            int j1 = __shfl_sync(FULL, myj, k + 1);
            float2 x0 = *(const float2*)(g_xl + (size_t)j0 * H_DIM + lane * 2);
            float2 x1 = *(const float2*)(g_xl + (size_t)j1 * H_DIM + lane * 2);
            float p0 = partial(x0);
            float p1 = partial(x1);
#pragma unroll
            for (int off = 16; off > 0; off >>= 1) {
                p0 += __shfl_xor_sync(FULL, p0, off);
                p1 += __shfl_xor_sync(FULL, p1, off);
            }
            update(p0, x0);
            update(p1, x1);
        }
        if (k < cnt) {
            int j0 = __shfl_sync(FULL, myj, k);
            float2 x0 = *(const float2*)(g_xl + (size_t)j0 * H_DIM + lane * 2);
            float p0 = partial(x0);
#pragma unroll
            for (int off = 16; off > 0; off >>= 1)
                p0 += __shfl_xor_sync(FULL, p0, off);
            update(p0, x0);
        }
    }

    const float inv = 1.f / d;
    float gb0 = gbias[lane * 2], gb1 = gbias[lane * 2 + 1];
    float o0 = fmaf(acc.x, inv, gb0);
    float o1 = fmaf(acc.y, inv, gb1);
    o0 = (o0 > 0.f) ? o0 : (__expf(o0) - 1.f);
    o1 = (o1 > 0.f) ? o1 : (__expf(o1) - 1.f);
    float2 r; r.x = o0; r.y = o1;
    *(float2*)(g_h + (size_t)i * H_DIM + lane * 2) = r;
}

// ============================================================
// 4) Output GEMM (VERBATIM from the passing R3/R9 kernel).
// ============================================================
__global__ void outgemm_kernel(const float* __restrict__ Wo,
                               const float* __restrict__ bo,
                               float* __restrict__ out, int N) {
    __shared__ float Ws[128 * 65];   // padded stride 65 (odd)
    __shared__ float hs[32 * 65];

    const int tid = threadIdx.x;
    const int n0 = blockIdx.x * 32;

    for (int i = tid; i < 128 * 64; i += 256) {
        int f = i >> 6, k = i & 63;
        Ws[f * 65 + k] = Wo[i];
    }
    for (int i = tid; i < 32 * 64; i += 256) {
        int n = i >> 6, k = i & 63;
        int node = n0 + n;
        hs[n * 65 + k] = (node < N) ? g_h[(size_t)node * H_DIM + k] : 0.f;
    }
    __syncthreads();

    const int tn = tid & 15;   // f = tn + 16*j
    const int tm = tid >> 4;   // n = tm + 16*i

    float acc[2][8];
#pragma unroll
    for (int i = 0; i < 2; i++)
#pragma unroll
        for (int j = 0; j < 8; j++) acc[i][j] = 0.f;

#pragma unroll 4
    for (int k = 0; k < H_DIM; k++) {
        float xv[2], wv[8];
#pragma unroll
        for (int i = 0; i < 2; i++) xv[i] = hs[(tm + 16 * i) * 65 + k];
#pragma unroll
        for (int j = 0; j < 8; j++) wv[j] = Ws[(tn + 16 * j) * 65 + k];
#pragma unroll
        for (int i = 0; i < 2; i++)
#pragma unroll
            for (int j = 0; j < 8; j++) acc[i][j] = fmaf(xv[i], wv[j], acc[i][j]);
    }

#pragma unroll
    for (int i = 0; i < 2; i++) {
        int node = n0 + tm + 16 * i;
        if (node >= N) continue;
#pragma unroll
        for (int j = 0; j < 8; j++) {
            int f = tn + 16 * j;
            out[(size_t)node * F_DIM + f] = acc[i][j] + bo[f];
        }
    }
}

// ============================================================
// 5) dispersion tail: softplus
// ============================================================
__global__ void disp_kernel(const float* __restrict__ disp, float* __restrict__ out) {
    int t = threadIdx.x;
    if (t < F_DIM) {
        float x = disp[t];
        out[t] = fmaxf(x, 0.f) + log1pf(__expf(-fabsf(x)));
    }
}

// ============================================================
extern "C" void kernel_launch(void* const* d_in, const int* in_sizes, int n_in,
                              void* d_out, int out_size) {
    const float*     xf   = (const float*)d_in[0];
    const float*     xb   = (const float*)d_in[1];
    const void*      ei   = d_in[2];
    const float*     Wl   = (const float*)d_in[3];
    const float*     bl   = (const float*)d_in[4];
    const float*     Wr   = (const float*)d_in[5];
    const float*     br   = (const float*)d_in[6];
    const float*     att  = (const float*)d_in[7];
    const float*     gb   = (const float*)d_in[8];
    const float*     Wo   = (const float*)d_in[9];
    const float*     bo   = (const float*)d_in[10];
    const float*     disp = (const float*)d_in[11];

    const int N = in_sizes[0] / F_DIM;
    const int E = in_sizes[2] / 2;
    const int NB = (N + 1023) / 1024;
    float* out = (float*)d_out;

    cudaFuncSetAttribute(proj_mma_kernel,
                         cudaFuncAttributeMaxDynamicSharedMemorySize, PROJ2_SMEM);

    detect_kernel<<<1, 32>>>((const int*)ei, 2 * E);
    convert_kernel<<<(2 * E + 255) / 256, 256>>>(ei, 2 * E);
    zero_deg_kernel<<<(N + 255) / 256, 256>>>(N);
    wconv_kernel<<<(128 * KPAD + 255) / 256, 256>>>(Wl, Wr, bl, br);
    proj_mma_kernel<<<(N + 63) / 64, 256, PROJ2_SMEM>>>(xf, xb, N);
    hist_kernel<<<(E + 255) / 256, 256>>>(E, N);
    scan_block_kernel<<<NB, 1024>>>(N);
    scan_tops_kernel<<<1, 64>>>(NB);
    scan_fix_kernel<<<(N + 255) / 256, 256>>>(N);
    scatter_kernel<<<(E + 255) / 256, 256>>>(E, N);
    agg_kernel<<<(N + 7) / 8, 256>>>(att, gb, N);
    outgemm_kernel<<<(N + 31) / 32, 256>>>(Wo, bo, out, N);
    disp_kernel<<<1, 128>>>(disp, out + (size_t)N * F_DIM);
}

// round 14
// speedup vs baseline: 1.9087x; 1.1845x over previous
#include <cuda_runtime.h>
#include <cuda_bf16.h>
#include <math.h>
#include <stdint.h>

// ---------------- problem constants ----------------
#define F_DIM 128
#define IN_DIM 129          // F_DIM + 1 (binary feature)
#define H_DIM 64
#define NEG_SLOPE 0.2f
#define N_MAX 50000
#define E_MAX 800000
#define KPAD 136            // padded K for proj bf16 tiles (272B rows)
#define KPAD2 72            // padded K for outgemm bf16 tiles (144B rows)

// ---------------- scratch (no allocations allowed) ----------------
__device__ __align__(16) float g_xl[N_MAX * H_DIM];
__device__ __align__(16) float g_xr[N_MAX * H_DIM];
__device__ __align__(16) float g_h [N_MAX * H_DIM];
__device__ int   g_deg[N_MAX];
__device__ int   g_rowptr[N_MAX + 1];
__device__ int   g_cursor[N_MAX];
__device__ int   g_adj[E_MAX];
__device__ __align__(16) int g_eidx[2 * E_MAX];
__device__ int   g_is64;
__device__ int   g_bsum[64];
__device__ int   g_boff[64];
// bf16-split weights
__device__ __align__(16) __nv_bfloat16 g_w_hi[128 * KPAD];
__device__ __align__(16) __nv_bfloat16 g_w_lo[128 * KPAD];
__device__ __align__(16) float g_wb[128];     // W[:,128] (binary-feature column)
__device__ __align__(16) float g_wbias[128];  // [bl; br]
__device__ __align__(16) __nv_bfloat16 g_wo_hi[128 * KPAD2];
__device__ __align__(16) __nv_bfloat16 g_wo_lo[128 * KPAD2];
__device__ __align__(16) float g_wob[128];    // bo

// ============================================================
// PTX helpers
// ============================================================
__device__ __forceinline__ uint32_t smem_u32(const void* p) {
    uint32_t a;
    asm("{ .reg .u64 t; cvta.to.shared.u64 t, %1; cvt.u32.u64 %0, t; }"
        : "=r"(a) : "l"(p));
    return a;
}

__device__ __forceinline__ void ldsm_x4(uint32_t& r0, uint32_t& r1,
                                        uint32_t& r2, uint32_t& r3, uint32_t addr) {
    asm volatile("ldmatrix.sync.aligned.m8n8.x4.shared.b16 {%0,%1,%2,%3}, [%4];"
                 : "=r"(r0), "=r"(r1), "=r"(r2), "=r"(r3) : "r"(addr));
}

__device__ __forceinline__ void mma16816(float& d0, float& d1, float& d2, float& d3,
                                         uint32_t a0, uint32_t a1, uint32_t a2, uint32_t a3,
                                         uint32_t b0, uint32_t b1) {
    asm volatile(
        "mma.sync.aligned.m16n8k16.row.col.f32.bf16.bf16.f32 "
        "{%0,%1,%2,%3},{%4,%5,%6,%7},{%8,%9},{%0,%1,%2,%3};"
        : "+f"(d0), "+f"(d1), "+f"(d2), "+f"(d3)
        : "r"(a0), "r"(a1), "r"(a2), "r"(a3), "r"(b0), "r"(b1));
}

// ============================================================
// 0) Edge dtype detection + conversion (hist fused into convert).
// ============================================================
__global__ void detect_kernel(const int* __restrict__ w, int nwords) {
    if (threadIdx.x == 0 && blockIdx.x == 0) {
        int is64 = 1;
        for (int i = 0; i < 64; i++) {
            int idx = 2 * i + 1;
            if (idx >= nwords) break;
            if (w[idx] != 0) { is64 = 0; break; }
        }
        g_is64 = is64;
    }
}

__global__ void convert_hist_kernel(const void* __restrict__ ei, int E, int N) {
    int e = blockIdx.x * blockDim.x + threadIdx.x;
    int total = 2 * E;
    if (e < total) {
        int v = g_is64 ? (int)((const long long*)ei)[e]
                       : ((const int*)ei)[e];
        g_eidx[e] = v;
        if (e >= E && (unsigned)v < (unsigned)N)   // dst half -> degree histogram
            atomicAdd(&g_deg[v], 1);
    }
}

// ============================================================
// 0b) Weight split: [Wl;Wr] and Wo -> hi/lo bf16 padded tiles,
//     plus f32 binary-column / bias arrays.
// ============================================================
__global__ void wconv_kernel(const float* __restrict__ Wl,
                             const float* __restrict__ Wr,
                             const float* __restrict__ bl,
                             const float* __restrict__ br,
                             const float* __restrict__ Wo,
                             const float* __restrict__ bo) {
    int idx = blockIdx.x * blockDim.x + threadIdx.x;
    if (idx < 128 * KPAD) {
        int h = idx / KPAD, kp = idx - h * KPAD;
        float v = 0.f;
        if (kp < 128) v = (h < 64) ? Wl[h * IN_DIM + kp] : Wr[(h - 64) * IN_DIM + kp];
        __nv_bfloat16 hi = __float2bfloat16(v);
        g_w_hi[idx] = hi;
        g_w_lo[idx] = __float2bfloat16(v - __bfloat162float(hi));
    }
    if (idx < 128 * KPAD2) {
        int f = idx / KPAD2, kp = idx - f * KPAD2;
        float v = (kp < H_DIM) ? Wo[f * H_DIM + kp] : 0.f;
        __nv_bfloat16 hi = __float2bfloat16(v);
        g_wo_hi[idx] = hi;
        g_wo_lo[idx] = __float2bfloat16(v - __bfloat162float(hi));
    }
    if (idx < 128) {
        g_wb[idx]    = (idx < 64) ? Wl[idx * IN_DIM + 128] : Wr[(idx - 64) * IN_DIM + 128];
        g_wbias[idx] = (idx < 64) ? bl[idx] : br[idx - 64];
        g_wob[idx]   = bo[idx];
    }
}

// ============================================================
// 1) Input projection via bf16-split tensor-core MMA (VERBATIM R13).
// ============================================================
#define SM_XH   0
#define SM_XL   17408
#define SM_WH   34816
#define SM_WL   69632
#define SM_XB   104448
#define SM_WB   104704
#define SM_BIAS 105216
#define PROJ2_SMEM 105728

__global__ __launch_bounds__(256) void proj_mma_kernel(
        const float* __restrict__ xf,
        const float* __restrict__ xb,
        int N) {
    extern __shared__ char smx[];
    __nv_bfloat16* xh = (__nv_bfloat16*)(smx + SM_XH);
    __nv_bfloat16* xl = (__nv_bfloat16*)(smx + SM_XL);
    float* xbs = (float*)(smx + SM_XB);
    float* wbs = (float*)(smx + SM_WB);
    float* bis = (float*)(smx + SM_BIAS);

    const int tid = threadIdx.x;
    const int n0 = blockIdx.x * 64;

    {
        const uint4* gwh = (const uint4*)g_w_hi;
        const uint4* gwl = (const uint4*)g_w_lo;
        uint4* swh = (uint4*)(smx + SM_WH);
        uint4* swl = (uint4*)(smx + SM_WL);
        for (int i = tid; i < 2176; i += 256) swh[i] = gwh[i];
        for (int i = tid; i < 2176; i += 256) swl[i] = gwl[i];
    }
    for (int i = tid; i < 64 * 128; i += 256) {
        int n = i >> 7, k = i & 127;
        int node = n0 + n;
        float v = (node < N) ? xf[(size_t)node * F_DIM + k] : 0.f;
        __nv_bfloat16 hi = __float2bfloat16(v);
        xh[n * KPAD + k] = hi;
        xl[n * KPAD + k] = __float2bfloat16(v - __bfloat162float(hi));
    }
    for (int i = tid; i < 64 * 8; i += 256) {
        int n = i >> 3, k = 128 + (i & 7);
        xh[n * KPAD + k] = __float2bfloat16(0.f);
        xl[n * KPAD + k] = __float2bfloat16(0.f);
    }
    if (tid < 64) {
        int node = n0 + tid;
        xbs[tid] = (node < N) ? xb[node] : 0.f;
    }
    if (tid < 128) { wbs[tid] = g_wb[tid]; bis[tid] = g_wbias[tid]; }
    __syncthreads();

    const int warp = tid >> 5, lane = tid & 31;
    const int mbase = (warp & 3) * 16;
    const int nwb   = (warp >> 2) * 64;

    float acc[8][4];
#pragma unroll
    for (int t = 0; t < 8; t++)
#pragma unroll
        for (int q = 0; q < 4; q++) acc[t][q] = 0.f;

    const uint32_t sb = smem_u32(smx);
    const uint32_t xh_a = sb + SM_XH, xl_a = sb + SM_XL;
    const uint32_t wh_a = sb + SM_WH, wl_a = sb + SM_WL;

    const int tr = lane & 7, tg = lane >> 3;
    const uint32_t aoff =
        ((uint32_t)((mbase + tr + (tg & 1) * 8) * KPAD + ((tg >> 1) * 8))) * 2u;
    uint32_t boff[4];
#pragma unroll
    for (int ng = 0; ng < 4; ng++)
        boff[ng] = ((uint32_t)((nwb + ng * 16 + tr + (tg >> 1) * 8) * KPAD
                               + ((tg & 1) * 8))) * 2u;

#pragma unroll
    for (int kc = 0; kc < 8; kc++) {
        const uint32_t kb = (uint32_t)kc * 32u;
        uint32_t ah0, ah1, ah2, ah3, al0, al1, al2, al3;
        ldsm_x4(ah0, ah1, ah2, ah3, xh_a + aoff + kb);
        ldsm_x4(al0, al1, al2, al3, xl_a + aoff + kb);
#pragma unroll
        for (int ng = 0; ng < 4; ng++) {
            uint32_t bh0, bh1, bh2, bh3, bl0_, bl1_, bl2_, bl3_;
            ldsm_x4(bh0, bh1, bh2, bh3, wh_a + boff[ng] + kb);
            ldsm_x4(bl0_, bl1_, bl2_, bl3_, wl_a + boff[ng] + kb);
            float* d0 = acc[ng * 2 + 0];
            float* d1 = acc[ng * 2 + 1];
            mma16816(d0[0], d0[1], d0[2], d0[3], ah0, ah1, ah2, ah3, bh0, bh1);
            mma16816(d1[0], d1[1], d1[2], d1[3], ah0, ah1, ah2, ah3, bh2, bh3);
            mma16816(d0[0], d0[1], d0[2], d0[3], ah0, ah1, ah2, ah3, bl0_, bl1_);
            mma16816(d1[0], d1[1], d1[2], d1[3], ah0, ah1, ah2, ah3, bl2_, bl3_);
            mma16816(d0[0], d0[1], d0[2], d0[3], al0, al1, al2, al3, bh0, bh1);
            mma16816(d1[0], d1[1], d1[2], d1[3], al0, al1, al2, al3, bh2, bh3);
        }
    }

    const int r = lane >> 2;
    const int cq = (lane & 3) * 2;
    const int mr0 = mbase + r, mr1 = mbase + r + 8;
    const int node0 = n0 + mr0, node1 = n0 + mr1;
    const float xb0 = xbs[mr0], xb1 = xbs[mr1];
#pragma unroll
    for (int nt = 0; nt < 8; nt++) {
        int h = nwb + nt * 8 + cq;
        float w0 = wbs[h], w1 = wbs[h + 1];
        float b0 = bis[h], b1 = bis[h + 1];
        float v0 = acc[nt][0] + xb0 * w0 + b0;
        float v1 = acc[nt][1] + xb0 * w1 + b1;
        float v2 = acc[nt][2] + xb1 * w0 + b0;
        float v3 = acc[nt][3] + xb1 * w1 + b1;
        float* base0;
        float* base1;
        if (h < H_DIM) {
            base0 = g_xl + (size_t)node0 * H_DIM + h;
            base1 = g_xl + (size_t)node1 * H_DIM + h;
        } else {
            base0 = g_xr + (size_t)node0 * H_DIM + (h - H_DIM);
            base1 = g_xr + (size_t)node1 * H_DIM + (h - H_DIM);
        }
        if (node0 < N) { float2 p; p.x = v0; p.y = v1; *(float2*)base0 = p; }
        if (node1 < N) { float2 p; p.x = v2; p.y = v3; *(float2*)base1 = p; }
    }
}

// ============================================================
// 2) CSR build (hist fused into convert above)
// ============================================================
__global__ void zero_deg_kernel(int N) {
    int i = blockIdx.x * blockDim.x + threadIdx.x;
    if (i < N) g_deg[i] = 0;
}

__global__ void scan_block_kernel(int N) {
    __shared__ int s[1024];
    const int b = blockIdx.x, t = threadIdx.x;
    const int idx = b * 1024 + t;
    int v = (idx < N) ? g_deg[idx] : 0;
    s[t] = v;
    __syncthreads();
    for (int off = 1; off < 1024; off <<= 1) {
        int x = (t >= off) ? s[t - off] : 0;
        __syncthreads();
        s[t] += x;
        __syncthreads();
    }
    if (idx < N) g_rowptr[idx + 1] = s[t];
    if (t == 1023) g_bsum[b] = s[1023];
}

__global__ void scan_tops_kernel(int NB) {
    __shared__ int s[64];
    const int t = threadIdx.x;
    int v = (t < NB) ? g_bsum[t] : 0;
    s[t] = v;
    __syncthreads();
    for (int off = 1; off < 64; off <<= 1) {
        int x = (t >= off) ? s[t - off] : 0;
        __syncthreads();
        s[t] += x;
        __syncthreads();
    }
    if (t < NB) g_boff[t] = s[t] - v;
}

__global__ void scan_fix_kernel(int N) {
    int i = blockIdx.x * blockDim.x + threadIdx.x;
    if (i < N) {
        int r = g_rowptr[i + 1] + g_boff[i >> 10];
        g_rowptr[i + 1] = r;
        g_cursor[i] = r - g_deg[i];
    }
    if (i == 0) g_rowptr[0] = 0;
}

__global__ void scatter_kernel(int E, int N) {
    int e = blockIdx.x * blockDim.x + threadIdx.x;
    if (e < E) {
        int s = g_eidx[e];
        int d = g_eidx[E + e];
        if ((unsigned)d < (unsigned)N && (unsigned)s < (unsigned)N) {
            int pos = atomicAdd(&g_cursor[d], 1);
            if (pos < E_MAX) g_adj[pos] = s;
        }
    }
}

// ============================================================
// 3) Per-node GATv2 attention + aggregation (VERBATIM from R9).
// ============================================================
__global__ void agg_kernel(const float* __restrict__ att,
                           const float* __restrict__ gbias, int N) {
    const int warp = (blockIdx.x * blockDim.x + threadIdx.x) >> 5;
    const int lane = threadIdx.x & 31;
    if (warp >= N) return;
    const int i = warp;
    const unsigned FULL = 0xffffffffu;

    const float2 xri = *(const float2*)(g_xr + (size_t)i * H_DIM + lane * 2);
    float2 a;  a.x = att[lane * 2];  a.y = att[lane * 2 + 1];
    const float2 xli = *(const float2*)(g_xl + (size_t)i * H_DIM + lane * 2);

    auto partial = [&](float2 xlj) -> float {
        float v0 = xlj.x + xri.x;
        float v1 = xlj.y + xri.y;
        v0 = (v0 > 0.f) ? v0 : NEG_SLOPE * v0;
        v1 = (v1 > 0.f) ? v1 : NEG_SLOPE * v1;
        return fmaf(v0, a.x, v1 * a.y);
    };

    float m;
    {
        float p = partial(xli);
#pragma unroll
        for (int off = 16; off > 0; off >>= 1)
            p += __shfl_xor_sync(FULL, p, off);
        m = p;
    }
    float d = 1.f;
    float2 acc = xli;

    auto update = [&](float sc, float2 xlj) {
        if (sc <= m) {
            float w = __expf(sc - m);
            d += w;
            acc.x = fmaf(w, xlj.x, acc.x);
            acc.y = fmaf(w, xlj.y, acc.y);
        } else {
            float scale = __expf(m - sc);
            d = fmaf(d, scale, 1.f);
            acc.x = fmaf(acc.x, scale, xlj.x);
            acc.y = fmaf(acc.y, scale, xlj.y);
            m = sc;
        }
    };

    const int s = g_rowptr[i], e = g_rowptr[i + 1];
    for (int b = s; b < e; b += 32) {
        int myj = (b + lane < e) ? g_adj[b + lane] : 0;
        int cnt = min(32, e - b);
        int k = 0;
        for (; k + 1 < cnt; k += 2) {
            int j0 = __shfl_sync(FULL, myj, k);
            int j1 = __shfl_sync(FULL, myj, k + 1);
            float2 x0 = *(const float2*)(g_xl + (size_t)j0 * H_DIM + lane * 2);
            float2 x1 = *(const float2*)(g_xl + (size_t)j1 * H_DIM + lane * 2);
            float p0 = partial(x0);
            float p1 = partial(x1);
#pragma unroll
            for (int off = 16; off > 0; off >>= 1) {
                p0 += __shfl_xor_sync(FULL, p0, off);
                p1 += __shfl_xor_sync(FULL, p1, off);
            }
            update(p0, x0);
            update(p1, x1);
        }
        if (k < cnt) {
            int j0 = __shfl_sync(FULL, myj, k);
            float2 x0 = *(const float2*)(g_xl + (size_t)j0 * H_DIM + lane * 2);
            float p0 = partial(x0);
#pragma unroll
            for (int off = 16; off > 0; off >>= 1)
                p0 += __shfl_xor_sync(FULL, p0, off);
            update(p0, x0);
        }
    }

    const float inv = 1.f / d;
    float gb0 = gbias[lane * 2], gb1 = gbias[lane * 2 + 1];
    float o0 = fmaf(acc.x, inv, gb0);
    float o1 = fmaf(acc.y, inv, gb1);
    o0 = (o0 > 0.f) ? o0 : (__expf(o0) - 1.f);
    o1 = (o1 > 0.f) ? o1 : (__expf(o1) - 1.f);
    float2 r; r.x = o0; r.y = o1;
    *(float2*)(g_h + (size_t)i * H_DIM + lane * 2) = r;
}

// ============================================================
// 4) Output GEMM via bf16-split MMA: logits = h[N,64] @ Wo^T + bo.
//    Same warp/fragment layout as proj_mma with K=64 (4 chunks),
//    KPAD2=72 (144B rows: ldmatrix rows -> banks 0,4,...,28).
// ============================================================
#define SO_HH   0
#define SO_HL   9216
#define SO_WH   18432
#define SO_WL   36864
#define SO_BIAS 55296
#define OUT2_SMEM 55808

__global__ __launch_bounds__(256) void outgemm_mma_kernel(
        float* __restrict__ out, int N) {
    extern __shared__ char smo[];
    __nv_bfloat16* hh = (__nv_bfloat16*)(smo + SO_HH);
    __nv_bfloat16* hl = (__nv_bfloat16*)(smo + SO_HL);
    float* bis = (float*)(smo + SO_BIAS);

    const int tid = threadIdx.x;
    const int n0 = blockIdx.x * 64;

    // stage Wo hi/lo (uint4 from 16B-aligned globals): 128*72*2/16 = 1152
    {
        const uint4* gwh = (const uint4*)g_wo_hi;
        const uint4* gwl = (const uint4*)g_wo_lo;
        uint4* swh = (uint4*)(smo + SO_WH);
        uint4* swl = (uint4*)(smo + SO_WL);
        for (int i = tid; i < 1152; i += 256) swh[i] = gwh[i];
        for (int i = tid; i < 1152; i += 256) swl[i] = gwl[i];
    }
    // stage + split h (float2 from my aligned g_h)
    for (int i = tid; i < 64 * 32; i += 256) {
        int n = i >> 5, q = i & 31;
        int node = n0 + n;
        float2 v = make_float2(0.f, 0.f);
        if (node < N) v = *(const float2*)(g_h + (size_t)node * H_DIM + q * 2);
        __nv_bfloat16 h0 = __float2bfloat16(v.x);
        __nv_bfloat16 h1 = __float2bfloat16(v.y);
        hh[n * KPAD2 + q * 2]     = h0;
        hh[n * KPAD2 + q * 2 + 1] = h1;
        hl[n * KPAD2 + q * 2]     = __float2bfloat16(v.x - __bfloat162float(h0));
        hl[n * KPAD2 + q * 2 + 1] = __float2bfloat16(v.y - __bfloat162float(h1));
    }
    for (int i = tid; i < 64 * 8; i += 256) {   // zero pad cols 64..71
        int n = i >> 3, k = 64 + (i & 7);
        hh[n * KPAD2 + k] = __float2bfloat16(0.f);
        hl[n * KPAD2 + k] = __float2bfloat16(0.f);
    }
    if (tid < 128) bis[tid] = g_wob[tid];
    __syncthreads();

    const int warp = tid >> 5, lane = tid & 31;
    const int mbase = (warp & 3) * 16;    // node rows
    const int nwb   = (warp >> 2) * 64;   // output cols

    float acc[8][4];
#pragma unroll
    for (int t = 0; t < 8; t++)
#pragma unroll
        for (int q = 0; q < 4; q++) acc[t][q] = 0.f;

    const uint32_t sb = smem_u32(smo);
    const uint32_t hh_a = sb + SO_HH, hl_a = sb + SO_HL;
    const uint32_t wh_a = sb + SO_WH, wl_a = sb + SO_WL;

    const int tr = lane & 7, tg = lane >> 3;
    const uint32_t aoff =
        ((uint32_t)((mbase + tr + (tg & 1) * 8) * KPAD2 + ((tg >> 1) * 8))) * 2u;
    uint32_t boff[4];
#pragma unroll
    for (int ng = 0; ng < 4; ng++)
        boff[ng] = ((uint32_t)((nwb + ng * 16 + tr + (tg >> 1) * 8) * KPAD2
                               + ((tg & 1) * 8))) * 2u;

#pragma unroll
    for (int kc = 0; kc < 4; kc++) {
        const uint32_t kb = (uint32_t)kc * 32u;
        uint32_t ah0, ah1, ah2, ah3, al0, al1, al2, al3;
        ldsm_x4(ah0, ah1, ah2, ah3, hh_a + aoff + kb);
        ldsm_x4(al0, al1, al2, al3, hl_a + aoff + kb);
#pragma unroll
        for (int ng = 0; ng < 4; ng++) {
            uint32_t bh0, bh1, bh2, bh3, bl0_, bl1_, bl2_, bl3_;
            ldsm_x4(bh0, bh1, bh2, bh3, wh_a + boff[ng] + kb);
            ldsm_x4(bl0_, bl1_, bl2_, bl3_, wl_a + boff[ng] + kb);
            float* d0 = acc[ng * 2 + 0];
            float* d1 = acc[ng * 2 + 1];
            mma16816(d0[0], d0[1], d0[2], d0[3], ah0, ah1, ah2, ah3, bh0, bh1);
            mma16816(d1[0], d1[1], d1[2], d1[3], ah0, ah1, ah2, ah3, bh2, bh3);
            mma16816(d0[0], d0[1], d0[2], d0[3], ah0, ah1, ah2, ah3, bl0_, bl1_);
            mma16816(d1[0], d1[1], d1[2], d1[3], ah0, ah1, ah2, ah3, bl2_, bl3_);
            mma16816(d0[0], d0[1], d0[2], d0[3], al0, al1, al2, al3, bh0, bh1);
            mma16816(d1[0], d1[1], d1[2], d1[3], al0, al1, al2, al3, bh2, bh3);
        }
    }

    // epilogue: + bo, scalar stores to out (alignment-unknown pointer)
    const int r = lane >> 2;
    const int cq = (lane & 3) * 2;
    const int mr0 = mbase + r, mr1 = mbase + r + 8;
    const int node0 = n0 + mr0, node1 = n0 + mr1;
#pragma unroll
    for (int nt = 0; nt < 8; nt++) {
        int f = nwb + nt * 8 + cq;
        float b0 = bis[f], b1 = bis[f + 1];
        if (node0 < N) {
            out[(size_t)node0 * F_DIM + f]     = acc[nt][0] + b0;
            out[(size_t)node0 * F_DIM + f + 1] = acc[nt][1] + b1;
        }
        if (node1 < N) {
            out[(size_t)node1 * F_DIM + f]     = acc[nt][2] + b0;
            out[(size_t)node1 * F_DIM + f + 1] = acc[nt][3] + b1;
        }
    }
}

// ============================================================
// 5) dispersion tail: softplus
// ============================================================
__global__ void disp_kernel(const float* __restrict__ disp, float* __restrict__ out) {
    int t = threadIdx.x;
    if (t < F_DIM) {
        float x = disp[t];
        out[t] = fmaxf(x, 0.f) + log1pf(__expf(-fabsf(x)));
    }
}

// ============================================================
extern "C" void kernel_launch(void* const* d_in, const int* in_sizes, int n_in,
                              void* d_out, int out_size) {
    const float*     xf   = (const float*)d_in[0];
    const float*     xb   = (const float*)d_in[1];
    const void*      ei   = d_in[2];
    const float*     Wl   = (const float*)d_in[3];
    const float*     bl   = (const float*)d_in[4];
    const float*     Wr   = (const float*)d_in[5];
    const float*     br   = (const float*)d_in[6];
    const float*     att  = (const float*)d_in[7];
    const float*     gb   = (const float*)d_in[8];
    const float*     Wo   = (const float*)d_in[9];
    const float*     bo   = (const float*)d_in[10];
    const float*     disp = (const float*)d_in[11];

    const int N = in_sizes[0] / F_DIM;
    const int E = in_sizes[2] / 2;
    const int NB = (N + 1023) / 1024;
    float* out = (float*)d_out;

    cudaFuncSetAttribute(proj_mma_kernel,
                         cudaFuncAttributeMaxDynamicSharedMemorySize, PROJ2_SMEM);
    cudaFuncSetAttribute(outgemm_mma_kernel,
                         cudaFuncAttributeMaxDynamicSharedMemorySize, OUT2_SMEM);

    detect_kernel<<<1, 32>>>((const int*)ei, 2 * E);
    zero_deg_kernel<<<(N + 255) / 256, 256>>>(N);
    convert_hist_kernel<<<(2 * E + 255) / 256, 256>>>(ei, E, N);
    wconv_kernel<<<(128 * KPAD + 255) / 256, 256>>>(Wl, Wr, bl, br, Wo, bo);
    proj_mma_kernel<<<(N + 63) / 64, 256, PROJ2_SMEM>>>(xf, xb, N);
    scan_block_kernel<<<NB, 1024>>>(N);
    scan_tops_kernel<<<1, 64>>>(NB);
    scan_fix_kernel<<<(N + 255) / 256, 256>>>(N);
    scatter_kernel<<<(E + 255) / 256, 256>>>(E, N);
    agg_kernel<<<(N + 7) / 8, 256>>>(att, gb, N);
    outgemm_mma_kernel<<<(N + 63) / 64, 256, OUT2_SMEM>>>(out, N);
    disp_kernel<<<1, 128>>>(disp, out + (size_t)N * F_DIM);
}

// round 15
// speedup vs baseline: 1.9435x; 1.0183x over previous
#include <cuda_runtime.h>
#include <cuda_bf16.h>
#include <math.h>
#include <stdint.h>

// ---------------- problem constants ----------------
#define F_DIM 128
#define IN_DIM 129          // F_DIM + 1 (binary feature)
#define H_DIM 64
#define NEG_SLOPE 0.2f
#define N_MAX 50000
#define E_MAX 800000
#define KPAD 136            // padded K for proj bf16 tiles (272B rows)
#define KPAD2 72            // padded K for outgemm bf16 tiles (144B rows)

// ---------------- scratch (no allocations allowed) ----------------
__device__ __align__(16) float g_xl[N_MAX * H_DIM];
__device__ __align__(16) float g_xr[N_MAX * H_DIM];
__device__ __align__(16) float g_h [N_MAX * H_DIM];
__device__ int   g_deg[N_MAX];
__device__ int   g_rowptr[N_MAX + 1];
__device__ int   g_cursor[N_MAX];
__device__ int   g_adj[E_MAX];
__device__ __align__(16) int g_eidx[2 * E_MAX];
__device__ int   g_is64;
__device__ int   g_bsum[64];
__device__ int   g_boff[64];
// bf16-split weights
__device__ __align__(16) __nv_bfloat16 g_w_hi[128 * KPAD];
__device__ __align__(16) __nv_bfloat16 g_w_lo[128 * KPAD];
__device__ __align__(16) float g_wb[128];     // W[:,128] (binary-feature column)
__device__ __align__(16) float g_wbias[128];  // [bl; br]
__device__ __align__(16) __nv_bfloat16 g_wo_hi[128 * KPAD2];
__device__ __align__(16) __nv_bfloat16 g_wo_lo[128 * KPAD2];
__device__ __align__(16) float g_wob[128];    // bo

// ============================================================
// PTX helpers
// ============================================================
__device__ __forceinline__ uint32_t smem_u32(const void* p) {
    uint32_t a;
    asm("{ .reg .u64 t; cvta.to.shared.u64 t, %1; cvt.u32.u64 %0, t; }"
        : "=r"(a) : "l"(p));
    return a;
}

__device__ __forceinline__ void ldsm_x4(uint32_t& r0, uint32_t& r1,
                                        uint32_t& r2, uint32_t& r3, uint32_t addr) {
    asm volatile("ldmatrix.sync.aligned.m8n8.x4.shared.b16 {%0,%1,%2,%3}, [%4];"
                 : "=r"(r0), "=r"(r1), "=r"(r2), "=r"(r3) : "r"(addr));
}

__device__ __forceinline__ void mma16816(float& d0, float& d1, float& d2, float& d3,
                                         uint32_t a0, uint32_t a1, uint32_t a2, uint32_t a3,
                                         uint32_t b0, uint32_t b1) {
    asm volatile(
        "mma.sync.aligned.m16n8k16.row.col.f32.bf16.bf16.f32 "
        "{%0,%1,%2,%3},{%4,%5,%6,%7},{%8,%9},{%0,%1,%2,%3};"
        : "+f"(d0), "+f"(d1), "+f"(d2), "+f"(d3)
        : "r"(a0), "r"(a1), "r"(a2), "r"(a3), "r"(b0), "r"(b1));
}

// ============================================================
// 0) Edge dtype detection + conversion (hist fused into convert).
// ============================================================
__global__ void detect_kernel(const int* __restrict__ w, int nwords) {
    if (threadIdx.x == 0 && blockIdx.x == 0) {
        int is64 = 1;
        for (int i = 0; i < 64; i++) {
            int idx = 2 * i + 1;
            if (idx >= nwords) break;
            if (w[idx] != 0) { is64 = 0; break; }
        }
        g_is64 = is64;
    }
}

__global__ void convert_hist_kernel(const void* __restrict__ ei, int E, int N) {
    int e = blockIdx.x * blockDim.x + threadIdx.x;
    int total = 2 * E;
    if (e < total) {
        int v = g_is64 ? (int)((const long long*)ei)[e]
                       : ((const int*)ei)[e];
        g_eidx[e] = v;
        if (e >= E && (unsigned)v < (unsigned)N)   // dst half -> degree histogram
            atomicAdd(&g_deg[v], 1);
    }
}

// ============================================================
// 0b) Weight split: [Wl;Wr] and Wo -> hi/lo bf16 padded tiles,
//     plus f32 binary-column / bias arrays.
// ============================================================
__global__ void wconv_kernel(const float* __restrict__ Wl,
                             const float* __restrict__ Wr,
                             const float* __restrict__ bl,
                             const float* __restrict__ br,
                             const float* __restrict__ Wo,
                             const float* __restrict__ bo) {
    int idx = blockIdx.x * blockDim.x + threadIdx.x;
    if (idx < 128 * KPAD) {
        int h = idx / KPAD, kp = idx - h * KPAD;
        float v = 0.f;
        if (kp < 128) v = (h < 64) ? Wl[h * IN_DIM + kp] : Wr[(h - 64) * IN_DIM + kp];
        __nv_bfloat16 hi = __float2bfloat16(v);
        g_w_hi[idx] = hi;
        g_w_lo[idx] = __float2bfloat16(v - __bfloat162float(hi));
    }
    if (idx < 128 * KPAD2) {
        int f = idx / KPAD2, kp = idx - f * KPAD2;
        float v = (kp < H_DIM) ? Wo[f * H_DIM + kp] : 0.f;
        __nv_bfloat16 hi = __float2bfloat16(v);
        g_wo_hi[idx] = hi;
        g_wo_lo[idx] = __float2bfloat16(v - __bfloat162float(hi));
    }
    if (idx < 128) {
        g_wb[idx]    = (idx < 64) ? Wl[idx * IN_DIM + 128] : Wr[(idx - 64) * IN_DIM + 128];
        g_wbias[idx] = (idx < 64) ? bl[idx] : br[idx - 64];
        g_wob[idx]   = bo[idx];
    }
}

// ============================================================
// 1) Input projection via bf16-split tensor-core MMA (VERBATIM R13).
// ============================================================
#define SM_XH   0
#define SM_XL   17408
#define SM_WH   34816
#define SM_WL   69632
#define SM_XB   104448
#define SM_WB   104704
#define SM_BIAS 105216
#define PROJ2_SMEM 105728

__global__ __launch_bounds__(256) void proj_mma_kernel(
        const float* __restrict__ xf,
        const float* __restrict__ xb,
        int N) {
    extern __shared__ char smx[];
    __nv_bfloat16* xh = (__nv_bfloat16*)(smx + SM_XH);
    __nv_bfloat16* xl = (__nv_bfloat16*)(smx + SM_XL);
    float* xbs = (float*)(smx + SM_XB);
    float* wbs = (float*)(smx + SM_WB);
    float* bis = (float*)(smx + SM_BIAS);

    const int tid = threadIdx.x;
    const int n0 = blockIdx.x * 64;

    {
        const uint4* gwh = (const uint4*)g_w_hi;
        const uint4* gwl = (const uint4*)g_w_lo;
        uint4* swh = (uint4*)(smx + SM_WH);
        uint4* swl = (uint4*)(smx + SM_WL);
        for (int i = tid; i < 2176; i += 256) swh[i] = gwh[i];
        for (int i = tid; i < 2176; i += 256) swl[i] = gwl[i];
    }
    for (int i = tid; i < 64 * 128; i += 256) {
        int n = i >> 7, k = i & 127;
        int node = n0 + n;
        float v = (node < N) ? xf[(size_t)node * F_DIM + k] : 0.f;
        __nv_bfloat16 hi = __float2bfloat16(v);
        xh[n * KPAD + k] = hi;
        xl[n * KPAD + k] = __float2bfloat16(v - __bfloat162float(hi));
    }
    for (int i = tid; i < 64 * 8; i += 256) {
        int n = i >> 3, k = 128 + (i & 7);
        xh[n * KPAD + k] = __float2bfloat16(0.f);
        xl[n * KPAD + k] = __float2bfloat16(0.f);
    }
    if (tid < 64) {
        int node = n0 + tid;
        xbs[tid] = (node < N) ? xb[node] : 0.f;
    }
    if (tid < 128) { wbs[tid] = g_wb[tid]; bis[tid] = g_wbias[tid]; }
    __syncthreads();

    const int warp = tid >> 5, lane = tid & 31;
    const int mbase = (warp & 3) * 16;
    const int nwb   = (warp >> 2) * 64;

    float acc[8][4];
#pragma unroll
    for (int t = 0; t < 8; t++)
#pragma unroll
        for (int q = 0; q < 4; q++) acc[t][q] = 0.f;

    const uint32_t sb = smem_u32(smx);
    const uint32_t xh_a = sb + SM_XH, xl_a = sb + SM_XL;
    const uint32_t wh_a = sb + SM_WH, wl_a = sb + SM_WL;

    const int tr = lane & 7, tg = lane >> 3;
    const uint32_t aoff =
        ((uint32_t)((mbase + tr + (tg & 1) * 8) * KPAD + ((tg >> 1) * 8))) * 2u;
    uint32_t boff[4];
#pragma unroll
    for (int ng = 0; ng < 4; ng++)
        boff[ng] = ((uint32_t)((nwb + ng * 16 + tr + (tg >> 1) * 8) * KPAD
                               + ((tg & 1) * 8))) * 2u;

#pragma unroll
    for (int kc = 0; kc < 8; kc++) {
        const uint32_t kb = (uint32_t)kc * 32u;
        uint32_t ah0, ah1, ah2, ah3, al0, al1, al2, al3;
        ldsm_x4(ah0, ah1, ah2, ah3, xh_a + aoff + kb);
        ldsm_x4(al0, al1, al2, al3, xl_a + aoff + kb);
#pragma unroll
        for (int ng = 0; ng < 4; ng++) {
            uint32_t bh0, bh1, bh2, bh3, bl0_, bl1_, bl2_, bl3_;
            ldsm_x4(bh0, bh1, bh2, bh3, wh_a + boff[ng] + kb);
            ldsm_x4(bl0_, bl1_, bl2_, bl3_, wl_a + boff[ng] + kb);
            float* d0 = acc[ng * 2 + 0];
            float* d1 = acc[ng * 2 + 1];
            mma16816(d0[0], d0[1], d0[2], d0[3], ah0, ah1, ah2, ah3, bh0, bh1);
            mma16816(d1[0], d1[1], d1[2], d1[3], ah0, ah1, ah2, ah3, bh2, bh3);
            mma16816(d0[0], d0[1], d0[2], d0[3], ah0, ah1, ah2, ah3, bl0_, bl1_);
            mma16816(d1[0], d1[1], d1[2], d1[3], ah0, ah1, ah2, ah3, bl2_, bl3_);
            mma16816(d0[0], d0[1], d0[2], d0[3], al0, al1, al2, al3, bh0, bh1);
            mma16816(d1[0], d1[1], d1[2], d1[3], al0, al1, al2, al3, bh2, bh3);
        }
    }

    const int r = lane >> 2;
    const int cq = (lane & 3) * 2;
    const int mr0 = mbase + r, mr1 = mbase + r + 8;
    const int node0 = n0 + mr0, node1 = n0 + mr1;
    const float xb0 = xbs[mr0], xb1 = xbs[mr1];
#pragma unroll
    for (int nt = 0; nt < 8; nt++) {
        int h = nwb + nt * 8 + cq;
        float w0 = wbs[h], w1 = wbs[h + 1];
        float b0 = bis[h], b1 = bis[h + 1];
        float v0 = acc[nt][0] + xb0 * w0 + b0;
        float v1 = acc[nt][1] + xb0 * w1 + b1;
        float v2 = acc[nt][2] + xb1 * w0 + b0;
        float v3 = acc[nt][3] + xb1 * w1 + b1;
        float* base0;
        float* base1;
        if (h < H_DIM) {
            base0 = g_xl + (size_t)node0 * H_DIM + h;
            base1 = g_xl + (size_t)node1 * H_DIM + h;
        } else {
            base0 = g_xr + (size_t)node0 * H_DIM + (h - H_DIM);
            base1 = g_xr + (size_t)node1 * H_DIM + (h - H_DIM);
        }
        if (node0 < N) { float2 p; p.x = v0; p.y = v1; *(float2*)base0 = p; }
        if (node1 < N) { float2 p; p.x = v2; p.y = v3; *(float2*)base1 = p; }
    }
}

// ============================================================
// 2) CSR build (hist fused into convert above)
// ============================================================
__global__ void zero_deg_kernel(int N) {
    int i = blockIdx.x * blockDim.x + threadIdx.x;
    if (i < N) g_deg[i] = 0;
}

__global__ void scan_block_kernel(int N) {
    __shared__ int s[1024];
    const int b = blockIdx.x, t = threadIdx.x;
    const int idx = b * 1024 + t;
    int v = (idx < N) ? g_deg[idx] : 0;
    s[t] = v;
    __syncthreads();
    for (int off = 1; off < 1024; off <<= 1) {
        int x = (t >= off) ? s[t - off] : 0;
        __syncthreads();
        s[t] += x;
        __syncthreads();
    }
    if (idx < N) g_rowptr[idx + 1] = s[t];
    if (t == 1023) g_bsum[b] = s[1023];
}

__global__ void scan_tops_kernel(int NB) {
    __shared__ int s[64];
    const int t = threadIdx.x;
    int v = (t < NB) ? g_bsum[t] : 0;
    s[t] = v;
    __syncthreads();
    for (int off = 1; off < 64; off <<= 1) {
        int x = (t >= off) ? s[t - off] : 0;
        __syncthreads();
        s[t] += x;
        __syncthreads();
    }
    if (t < NB) g_boff[t] = s[t] - v;
}

__global__ void scan_fix_kernel(int N) {
    int i = blockIdx.x * blockDim.x + threadIdx.x;
    if (i < N) {
        int r = g_rowptr[i + 1] + g_boff[i >> 10];
        g_rowptr[i + 1] = r;
        g_cursor[i] = r - g_deg[i];
    }
    if (i == 0) g_rowptr[0] = 0;
}

__global__ void scatter_kernel(int E, int N) {
    int e = blockIdx.x * blockDim.x + threadIdx.x;
    if (e < E) {
        int s = g_eidx[e];
        int d = g_eidx[E + e];
        if ((unsigned)d < (unsigned)N && (unsigned)s < (unsigned)N) {
            int pos = atomicAdd(&g_cursor[d], 1);
            if (pos < E_MAX) g_adj[pos] = s;
        }
    }
}

// ============================================================
// 3) Per-node GATv2 attention + aggregation (VERBATIM from R9).
// ============================================================
__global__ void agg_kernel(const float* __restrict__ att,
                           const float* __restrict__ gbias, int N) {
    const int warp = (blockIdx.x * blockDim.x + threadIdx.x) >> 5;
    const int lane = threadIdx.x & 31;
    if (warp >= N) return;
    const int i = warp;
    const unsigned FULL = 0xffffffffu;

    const float2 xri = *(const float2*)(g_xr + (size_t)i * H_DIM + lane * 2);
    float2 a;  a.x = att[lane * 2];  a.y = att[lane * 2 + 1];
    const float2 xli = *(const float2*)(g_xl + (size_t)i * H_DIM + lane * 2);

    auto partial = [&](float2 xlj) -> float {
        float v0 = xlj.x + xri.x;
        float v1 = xlj.y + xri.y;
        v0 = (v0 > 0.f) ? v0 : NEG_SLOPE * v0;
        v1 = (v1 > 0.f) ? v1 : NEG_SLOPE * v1;
        return fmaf(v0, a.x, v1 * a.y);
    };

    float m;
    {
        float p = partial(xli);
#pragma unroll
        for (int off = 16; off > 0; off >>= 1)
            p += __shfl_xor_sync(FULL, p, off);
        m = p;
    }
    float d = 1.f;
    float2 acc = xli;

    auto update = [&](float sc, float2 xlj) {
        if (sc <= m) {
            float w = __expf(sc - m);
            d += w;
            acc.x = fmaf(w, xlj.x, acc.x);
            acc.y = fmaf(w, xlj.y, acc.y);
        } else {
            float scale = __expf(m - sc);
            d = fmaf(d, scale, 1.f);
            acc.x = fmaf(acc.x, scale, xlj.x);
            acc.y = fmaf(acc.y, scale, xlj.y);
            m = sc;
        }
    };

    const int s = g_rowptr[i], e = g_rowptr[i + 1];
    for (int b = s; b < e; b += 32) {
        int myj = (b + lane < e) ? g_adj[b + lane] : 0;
        int cnt = min(32, e - b);
        int k = 0;
        for (; k + 1 < cnt; k += 2) {
            int j0 = __shfl_sync(FULL, myj, k);
            int j1 = __shfl_sync(FULL, myj, k + 1);
            float2 x0 = *(const float2*)(g_xl + (size_t)j0 * H_DIM + lane * 2);
            float2 x1 = *(const float2*)(g_xl + (size_t)j1 * H_DIM + lane * 2);
            float p0 = partial(x0);
            float p1 = partial(x1);
#pragma unroll
            for (int off = 16; off > 0; off >>= 1) {
                p0 += __shfl_xor_sync(FULL, p0, off);
                p1 += __shfl_xor_sync(FULL, p1, off);
            }
            update(p0, x0);
            update(p1, x1);
        }
        if (k < cnt) {
            int j0 = __shfl_sync(FULL, myj, k);
            float2 x0 = *(const float2*)(g_xl + (size_t)j0 * H_DIM + lane * 2);
            float p0 = partial(x0);
#pragma unroll
            for (int off = 16; off > 0; off >>= 1)
                p0 += __shfl_xor_sync(FULL, p0, off);
            update(p0, x0);
        }
    }

    const float inv = 1.f / d;
    float gb0 = gbias[lane * 2], gb1 = gbias[lane * 2 + 1];
    float o0 = fmaf(acc.x, inv, gb0);
    float o1 = fmaf(acc.y, inv, gb1);
    o0 = (o0 > 0.f) ? o0 : (__expf(o0) - 1.f);
    o1 = (o1 > 0.f) ? o1 : (__expf(o1) - 1.f);
    float2 r; r.x = o0; r.y = o1;
    *(float2*)(g_h + (size_t)i * H_DIM + lane * 2) = r;
}

// ============================================================
// 4) Output GEMM via bf16-split MMA (VERBATIM from R14).
// ============================================================
#define SO_HH   0
#define SO_HL   9216
#define SO_WH   18432
#define SO_WL   36864
#define SO_BIAS 55296
#define OUT2_SMEM 55808

__global__ __launch_bounds__(256) void outgemm_mma_kernel(
        float* __restrict__ out, int N) {
    extern __shared__ char smo[];
    __nv_bfloat16* hh = (__nv_bfloat16*)(smo + SO_HH);
    __nv_bfloat16* hl = (__nv_bfloat16*)(smo + SO_HL);
    float* bis = (float*)(smo + SO_BIAS);

    const int tid = threadIdx.x;
    const int n0 = blockIdx.x * 64;

    {
        const uint4* gwh = (const uint4*)g_wo_hi;
        const uint4* gwl = (const uint4*)g_wo_lo;
        uint4* swh = (uint4*)(smo + SO_WH);
        uint4* swl = (uint4*)(smo + SO_WL);
        for (int i = tid; i < 1152; i += 256) swh[i] = gwh[i];
        for (int i = tid; i < 1152; i += 256) swl[i] = gwl[i];
    }
    for (int i = tid; i < 64 * 32; i += 256) {
        int n = i >> 5, q = i & 31;
        int node = n0 + n;
        float2 v = make_float2(0.f, 0.f);
        if (node < N) v = *(const float2*)(g_h + (size_t)node * H_DIM + q * 2);
        __nv_bfloat16 h0 = __float2bfloat16(v.x);
        __nv_bfloat16 h1 = __float2bfloat16(v.y);
        hh[n * KPAD2 + q * 2]     = h0;
        hh[n * KPAD2 + q * 2 + 1] = h1;
        hl[n * KPAD2 + q * 2]     = __float2bfloat16(v.x - __bfloat162float(h0));
        hl[n * KPAD2 + q * 2 + 1] = __float2bfloat16(v.y - __bfloat162float(h1));
    }
    for (int i = tid; i < 64 * 8; i += 256) {
        int n = i >> 3, k = 64 + (i & 7);
        hh[n * KPAD2 + k] = __float2bfloat16(0.f);
        hl[n * KPAD2 + k] = __float2bfloat16(0.f);
    }
    if (tid < 128) bis[tid] = g_wob[tid];
    __syncthreads();

    const int warp = tid >> 5, lane = tid & 31;
    const int mbase = (warp & 3) * 16;
    const int nwb   = (warp >> 2) * 64;

    float acc[8][4];
#pragma unroll
    for (int t = 0; t < 8; t++)
#pragma unroll
        for (int q = 0; q < 4; q++) acc[t][q] = 0.f;

    const uint32_t sb = smem_u32(smo);
    const uint32_t hh_a = sb + SO_HH, hl_a = sb + SO_HL;
    const uint32_t wh_a = sb + SO_WH, wl_a = sb + SO_WL;

    const int tr = lane & 7, tg = lane >> 3;
    const uint32_t aoff =
        ((uint32_t)((mbase + tr + (tg & 1) * 8) * KPAD2 + ((tg >> 1) * 8))) * 2u;
    uint32_t boff[4];
#pragma unroll
    for (int ng = 0; ng < 4; ng++)
        boff[ng] = ((uint32_t)((nwb + ng * 16 + tr + (tg >> 1) * 8) * KPAD2
                               + ((tg & 1) * 8))) * 2u;

#pragma unroll
    for (int kc = 0; kc < 4; kc++) {
        const uint32_t kb = (uint32_t)kc * 32u;
        uint32_t ah0, ah1, ah2, ah3, al0, al1, al2, al3;
        ldsm_x4(ah0, ah1, ah2, ah3, hh_a + aoff + kb);
        ldsm_x4(al0, al1, al2, al3, hl_a + aoff + kb);
#pragma unroll
        for (int ng = 0; ng < 4; ng++) {
            uint32_t bh0, bh1, bh2, bh3, bl0_, bl1_, bl2_, bl3_;
            ldsm_x4(bh0, bh1, bh2, bh3, wh_a + boff[ng] + kb);
            ldsm_x4(bl0_, bl1_, bl2_, bl3_, wl_a + boff[ng] + kb);
            float* d0 = acc[ng * 2 + 0];
            float* d1 = acc[ng * 2 + 1];
            mma16816(d0[0], d0[1], d0[2], d0[3], ah0, ah1, ah2, ah3, bh0, bh1);
            mma16816(d1[0], d1[1], d1[2], d1[3], ah0, ah1, ah2, ah3, bh2, bh3);
            mma16816(d0[0], d0[1], d0[2], d0[3], ah0, ah1, ah2, ah3, bl0_, bl1_);
            mma16816(d1[0], d1[1], d1[2], d1[3], ah0, ah1, ah2, ah3, bl2_, bl3_);
            mma16816(d0[0], d0[1], d0[2], d0[3], al0, al1, al2, al3, bh0, bh1);
            mma16816(d1[0], d1[1], d1[2], d1[3], al0, al1, al2, al3, bh2, bh3);
        }
    }

    const int r = lane >> 2;
    const int cq = (lane & 3) * 2;
    const int mr0 = mbase + r, mr1 = mbase + r + 8;
    const int node0 = n0 + mr0, node1 = n0 + mr1;
#pragma unroll
    for (int nt = 0; nt < 8; nt++) {
        int f = nwb + nt * 8 + cq;
        float b0 = bis[f], b1 = bis[f + 1];
        if (node0 < N) {
            out[(size_t)node0 * F_DIM + f]     = acc[nt][0] + b0;
            out[(size_t)node0 * F_DIM + f + 1] = acc[nt][1] + b1;
        }
        if (node1 < N) {
            out[(size_t)node1 * F_DIM + f]     = acc[nt][2] + b0;
            out[(size_t)node1 * F_DIM + f + 1] = acc[nt][3] + b1;
        }
    }
}

// ============================================================
// 5) dispersion tail: softplus
// ============================================================
__global__ void disp_kernel(const float* __restrict__ disp, float* __restrict__ out) {
    int t = threadIdx.x;
    if (t < F_DIM) {
        float x = disp[t];
        out[t] = fmaxf(x, 0.f) + log1pf(__expf(-fabsf(x)));
    }
}

// ============================================================
// Stream/event singletons: created lazily on the FIRST call
// (the harness's correctness run, which is NOT graph-captured),
// then reused inside capture via the documented fork-join pattern.
// ============================================================
static cudaStream_t g_s2 = 0;
static cudaEvent_t  g_evF = 0, g_evJ = 0;

extern "C" void kernel_launch(void* const* d_in, const int* in_sizes, int n_in,
                              void* d_out, int out_size) {
    const float*     xf   = (const float*)d_in[0];
    const float*     xb   = (const float*)d_in[1];
    const void*      ei   = d_in[2];
    const float*     Wl   = (const float*)d_in[3];
    const float*     bl   = (const float*)d_in[4];
    const float*     Wr   = (const float*)d_in[5];
    const float*     br   = (const float*)d_in[6];
    const float*     att  = (const float*)d_in[7];
    const float*     gb   = (const float*)d_in[8];
    const float*     Wo   = (const float*)d_in[9];
    const float*     bo   = (const float*)d_in[10];
    const float*     disp = (const float*)d_in[11];

    const int N = in_sizes[0] / F_DIM;
    const int E = in_sizes[2] / 2;
    const int NB = (N + 1023) / 1024;
    float* out = (float*)d_out;

    if (!g_s2) {
        cudaStreamCreateWithFlags(&g_s2, cudaStreamNonBlocking);
        cudaEventCreateWithFlags(&g_evF, cudaEventDisableTiming);
        cudaEventCreateWithFlags(&g_evJ, cudaEventDisableTiming);
        cudaFuncSetAttribute(proj_mma_kernel,
                             cudaFuncAttributeMaxDynamicSharedMemorySize, PROJ2_SMEM);
        cudaFuncSetAttribute(outgemm_mma_kernel,
                             cudaFuncAttributeMaxDynamicSharedMemorySize, OUT2_SMEM);
    }

    // ---- fork: proj chain on s2, CSR chain on default ----
    cudaEventRecord(g_evF, 0);
    cudaStreamWaitEvent(g_s2, g_evF, 0);

    // s2: weight split -> projection MMA
    wconv_kernel<<<(128 * KPAD + 255) / 256, 256, 0, g_s2>>>(Wl, Wr, bl, br, Wo, bo);
    proj_mma_kernel<<<(N + 63) / 64, 256, PROJ2_SMEM, g_s2>>>(xf, xb, N);
    cudaEventRecord(g_evJ, g_s2);

    // default: edge conversion + CSR build
    detect_kernel<<<1, 32>>>((const int*)ei, 2 * E);
    zero_deg_kernel<<<(N + 255) / 256, 256>>>(N);
    convert_hist_kernel<<<(2 * E + 255) / 256, 256>>>(ei, E, N);
    scan_block_kernel<<<NB, 1024>>>(N);
    scan_tops_kernel<<<1, 64>>>(NB);
    scan_fix_kernel<<<(N + 255) / 256, 256>>>(N);
    scatter_kernel<<<(E + 255) / 256, 256>>>(E, N);

    // ---- join: agg needs proj + CSR ----
    cudaStreamWaitEvent(0, g_evJ, 0);
    agg_kernel<<<(N + 7) / 8, 256>>>(att, gb, N);
    outgemm_mma_kernel<<<(N + 63) / 64, 256, OUT2_SMEM>>>(out, N);
    disp_kernel<<<1, 128>>>(disp, out + (size_t)N * F_DIM);
}

// round 17
// speedup vs baseline: 2.0280x; 1.0435x over previous
#include <cuda_runtime.h>
#include <cuda_bf16.h>
#include <math.h>
#include <stdint.h>

// ---------------- problem constants ----------------
#define F_DIM 128
#define IN_DIM 129          // F_DIM + 1 (binary feature)
#define H_DIM 64
#define NEG_SLOPE 0.2f
#define N_MAX 50000
#define E_MAX 800000
#define KPAD 136            // padded K for proj bf16 tiles (272B rows)
#define KPAD2 72            // padded K for outgemm bf16 tiles (144B rows)

// ---------------- scratch (no allocations allowed) ----------------
__device__ __align__(16) float g_xl[N_MAX * H_DIM];
__device__ __align__(16) float g_xr[N_MAX * H_DIM];
__device__ __align__(16) float g_h [N_MAX * H_DIM];
__device__ int   g_deg[N_MAX];
__device__ int   g_rowptr[N_MAX + 1];
__device__ int   g_cursor[N_MAX];
__device__ int   g_adj[E_MAX];
__device__ __align__(16) int g_eidx[2 * E_MAX];
__device__ int   g_is64;
__device__ int   g_bsum[64];
// bf16-split weights
__device__ __align__(16) __nv_bfloat16 g_w_hi[128 * KPAD];
__device__ __align__(16) __nv_bfloat16 g_w_lo[128 * KPAD];
__device__ __align__(16) float g_wb[128];     // W[:,128] (binary-feature column)
__device__ __align__(16) float g_wbias[128];  // [bl; br]
__device__ __align__(16) __nv_bfloat16 g_wo_hi[128 * KPAD2];
__device__ __align__(16) __nv_bfloat16 g_wo_lo[128 * KPAD2];
__device__ __align__(16) float g_wob[128];    // bo

// ============================================================
// PTX helpers
// ============================================================
__device__ __forceinline__ uint32_t smem_u32(const void* p) {
    uint32_t a;
    asm("{ .reg .u64 t; cvta.to.shared.u64 t, %1; cvt.u32.u64 %0, t; }"
        : "=r"(a) : "l"(p));
    return a;
}

__device__ __forceinline__ void ldsm_x4(uint32_t& r0, uint32_t& r1,
                                        uint32_t& r2, uint32_t& r3, uint32_t addr) {
    asm volatile("ldmatrix.sync.aligned.m8n8.x4.shared.b16 {%0,%1,%2,%3}, [%4];"
                 : "=r"(r0), "=r"(r1), "=r"(r2), "=r"(r3) : "r"(addr));
}

__device__ __forceinline__ void mma16816(float& d0, float& d1, float& d2, float& d3,
                                         uint32_t a0, uint32_t a1, uint32_t a2, uint32_t a3,
                                         uint32_t b0, uint32_t b1) {
    asm volatile(
        "mma.sync.aligned.m16n8k16.row.col.f32.bf16.bf16.f32 "
        "{%0,%1,%2,%3},{%4,%5,%6,%7},{%8,%9},{%0,%1,%2,%3};"
        : "+f"(d0), "+f"(d1), "+f"(d2), "+f"(d3)
        : "r"(a0), "r"(a1), "r"(a2), "r"(a3), "r"(b0), "r"(b1));
}

// ============================================================
// 0) zero g_deg + edge dtype detection (merged: saves a launch)
// ============================================================
__global__ void zero_detect_kernel(const int* __restrict__ w, int nwords, int N) {
    int i = blockIdx.x * blockDim.x + threadIdx.x;
    if (i < N) g_deg[i] = 0;
    if (i == 0) {
        int is64 = 1;
        for (int q = 0; q < 64; q++) {
            int idx = 2 * q + 1;
            if (idx >= nwords) break;
            if (w[idx] != 0) { is64 = 0; break; }
        }
        g_is64 = is64;
    }
}

__global__ void convert_hist_kernel(const void* __restrict__ ei, int E, int N) {
    int e = blockIdx.x * blockDim.x + threadIdx.x;
    int total = 2 * E;
    if (e < total) {
        int v = g_is64 ? (int)((const long long*)ei)[e]
                       : ((const int*)ei)[e];
        g_eidx[e] = v;
        if (e >= E && (unsigned)v < (unsigned)N)   // dst half -> degree histogram
            atomicAdd(&g_deg[v], 1);
    }
}

// ============================================================
// 0b) Weight split (VERBATIM R14).
// ============================================================
__global__ void wconv_kernel(const float* __restrict__ Wl,
                             const float* __restrict__ Wr,
                             const float* __restrict__ bl,
                             const float* __restrict__ br,
                             const float* __restrict__ Wo,
                             const float* __restrict__ bo) {
    int idx = blockIdx.x * blockDim.x + threadIdx.x;
    if (idx < 128 * KPAD) {
        int h = idx / KPAD, kp = idx - h * KPAD;
        float v = 0.f;
        if (kp < 128) v = (h < 64) ? Wl[h * IN_DIM + kp] : Wr[(h - 64) * IN_DIM + kp];
        __nv_bfloat16 hi = __float2bfloat16(v);
        g_w_hi[idx] = hi;
        g_w_lo[idx] = __float2bfloat16(v - __bfloat162float(hi));
    }
    if (idx < 128 * KPAD2) {
        int f = idx / KPAD2, kp = idx - f * KPAD2;
        float v = (kp < H_DIM) ? Wo[f * H_DIM + kp] : 0.f;
        __nv_bfloat16 hi = __float2bfloat16(v);
        g_wo_hi[idx] = hi;
        g_wo_lo[idx] = __float2bfloat16(v - __bfloat162float(hi));
    }
    if (idx < 128) {
        g_wb[idx]    = (idx < 64) ? Wl[idx * IN_DIM + 128] : Wr[(idx - 64) * IN_DIM + 128];
        g_wbias[idx] = (idx < 64) ? bl[idx] : br[idx - 64];
        g_wob[idx]   = bo[idx];
    }
}

// ============================================================
// 1) Input projection via bf16-split tensor-core MMA (VERBATIM R13).
// ============================================================
#define SM_XH   0
#define SM_XL   17408
#define SM_WH   34816
#define SM_WL   69632
#define SM_XB   104448
#define SM_WB   104704
#define SM_BIAS 105216
#define PROJ2_SMEM 105728

__global__ __launch_bounds__(256) void proj_mma_kernel(
        const float* __restrict__ xf,
        const float* __restrict__ xb,
        int N) {
    extern __shared__ char smx[];
    __nv_bfloat16* xh = (__nv_bfloat16*)(smx + SM_XH);
    __nv_bfloat16* xl = (__nv_bfloat16*)(smx + SM_XL);
    float* xbs = (float*)(smx + SM_XB);
    float* wbs = (float*)(smx + SM_WB);
    float* bis = (float*)(smx + SM_BIAS);

    const int tid = threadIdx.x;
    const int n0 = blockIdx.x * 64;

    {
        const uint4* gwh = (const uint4*)g_w_hi;
        const uint4* gwl = (const uint4*)g_w_lo;
        uint4* swh = (uint4*)(smx + SM_WH);
        uint4* swl = (uint4*)(smx + SM_WL);
        for (int i = tid; i < 2176; i += 256) swh[i] = gwh[i];
        for (int i = tid; i < 2176; i += 256) swl[i] = gwl[i];
    }
    for (int i = tid; i < 64 * 128; i += 256) {
        int n = i >> 7, k = i & 127;
        int node = n0 + n;
        float v = (node < N) ? xf[(size_t)node * F_DIM + k] : 0.f;
        __nv_bfloat16 hi = __float2bfloat16(v);
        xh[n * KPAD + k] = hi;
        xl[n * KPAD + k] = __float2bfloat16(v - __bfloat162float(hi));
    }
    for (int i = tid; i < 64 * 8; i += 256) {
        int n = i >> 3, k = 128 + (i & 7);
        xh[n * KPAD + k] = __float2bfloat16(0.f);
        xl[n * KPAD + k] = __float2bfloat16(0.f);
    }
    if (tid < 64) {
        int node = n0 + tid;
        xbs[tid] = (node < N) ? xb[node] : 0.f;
    }
    if (tid < 128) { wbs[tid] = g_wb[tid]; bis[tid] = g_wbias[tid]; }
    __syncthreads();

    const int warp = tid >> 5, lane = tid & 31;
    const int mbase = (warp & 3) * 16;
    const int nwb   = (warp >> 2) * 64;

    float acc[8][4];
#pragma unroll
    for (int t = 0; t < 8; t++)
#pragma unroll
        for (int q = 0; q < 4; q++) acc[t][q] = 0.f;

    const uint32_t sb = smem_u32(smx);
    const uint32_t xh_a = sb + SM_XH, xl_a = sb + SM_XL;
    const uint32_t wh_a = sb + SM_WH, wl_a = sb + SM_WL;

    const int tr = lane & 7, tg = lane >> 3;
    const uint32_t aoff =
        ((uint32_t)((mbase + tr + (tg & 1) * 8) * KPAD + ((tg >> 1) * 8))) * 2u;
    uint32_t boff[4];
#pragma unroll
    for (int ng = 0; ng < 4; ng++)
        boff[ng] = ((uint32_t)((nwb + ng * 16 + tr + (tg >> 1) * 8) * KPAD
                               + ((tg & 1) * 8))) * 2u;

#pragma unroll
    for (int kc = 0; kc < 8; kc++) {
        const uint32_t kb = (uint32_t)kc * 32u;
        uint32_t ah0, ah1, ah2, ah3, al0, al1, al2, al3;
        ldsm_x4(ah0, ah1, ah2, ah3, xh_a + aoff + kb);
        ldsm_x4(al0, al1, al2, al3, xl_a + aoff + kb);
#pragma unroll
        for (int ng = 0; ng < 4; ng++) {
            uint32_t bh0, bh1, bh2, bh3, bl0_, bl1_, bl2_, bl3_;
            ldsm_x4(bh0, bh1, bh2, bh3, wh_a + boff[ng] + kb);
            ldsm_x4(bl0_, bl1_, bl2_, bl3_, wl_a + boff[ng] + kb);
            float* d0 = acc[ng * 2 + 0];
            float* d1 = acc[ng * 2 + 1];
            mma16816(d0[0], d0[1], d0[2], d0[3], ah0, ah1, ah2, ah3, bh0, bh1);
            mma16816(d1[0], d1[1], d1[2], d1[3], ah0, ah1, ah2, ah3, bh2, bh3);
            mma16816(d0[0], d0[1], d0[2], d0[3], ah0, ah1, ah2, ah3, bl0_, bl1_);
            mma16816(d1[0], d1[1], d1[2], d1[3], ah0, ah1, ah2, ah3, bl2_, bl3_);
            mma16816(d0[0], d0[1], d0[2], d0[3], al0, al1, al2, al3, bh0, bh1);
            mma16816(d1[0], d1[1], d1[2], d1[3], al0, al1, al2, al3, bh2, bh3);
        }
    }

    const int r = lane >> 2;
    const int cq = (lane & 3) * 2;
    const int mr0 = mbase + r, mr1 = mbase + r + 8;
    const int node0 = n0 + mr0, node1 = n0 + mr1;
    const float xb0 = xbs[mr0], xb1 = xbs[mr1];
#pragma unroll
    for (int nt = 0; nt < 8; nt++) {
        int h = nwb + nt * 8 + cq;
        float w0 = wbs[h], w1 = wbs[h + 1];
        float b0 = bis[h], b1 = bis[h + 1];
        float v0 = acc[nt][0] + xb0 * w0 + b0;
        float v1 = acc[nt][1] + xb0 * w1 + b1;
        float v2 = acc[nt][2] + xb1 * w0 + b0;
        float v3 = acc[nt][3] + xb1 * w1 + b1;
        float* base0;
        float* base1;
        if (h < H_DIM) {
            base0 = g_xl + (size_t)node0 * H_DIM + h;
            base1 = g_xl + (size_t)node1 * H_DIM + h;
        } else {
            base0 = g_xr + (size_t)node0 * H_DIM + (h - H_DIM);
            base1 = g_xr + (size_t)node1 * H_DIM + (h - H_DIM);
        }
        if (node0 < N) { float2 p; p.x = v0; p.y = v1; *(float2*)base0 = p; }
        if (node1 < N) { float2 p; p.x = v2; p.y = v3; *(float2*)base1 = p; }
    }
}

// ============================================================
// 2) CSR build
// ============================================================
__global__ void scan_block_kernel(int N) {
    __shared__ int s[1024];
    const int b = blockIdx.x, t = threadIdx.x;
    const int idx = b * 1024 + t;
    int v = (idx < N) ? g_deg[idx] : 0;
    s[t] = v;
    __syncthreads();
    for (int off = 1; off < 1024; off <<= 1) {
        int x = (t >= off) ? s[t - off] : 0;
        __syncthreads();
        s[t] += x;
        __syncthreads();
    }
    if (idx < N) g_rowptr[idx + 1] = s[t];
    if (t == 1023) g_bsum[b] = s[1023];
}

// fix with block-sum scan folded in (each block redundantly scans the
// 64 block sums in smem; saves the scan_tops launch)
__global__ void scan_fix_kernel(int N, int NB) {
    __shared__ int sb[64];
    __shared__ int sex[64];
    const int t = threadIdx.x;
    int v0 = 0;
    if (t < 64) {
        v0 = (t < NB) ? g_bsum[t] : 0;
        sb[t] = v0;
    }
    __syncthreads();
    for (int off = 1; off < 64; off <<= 1) {
        int x = (t >= off && t < 64) ? sb[t - off] : 0;
        __syncthreads();
        if (t < 64) sb[t] += x;
        __syncthreads();
    }
    if (t < 64) sex[t] = sb[t] - v0;   // exclusive prefix
    __syncthreads();

    int i = blockIdx.x * blockDim.x + t;
    if (i < N) {
        int r = g_rowptr[i + 1] + sex[i >> 10];
        g_rowptr[i + 1] = r;
        g_cursor[i] = r - g_deg[i];
    }
    if (i == 0) g_rowptr[0] = 0;
}

__global__ void scatter_kernel(int E, int N) {
    int e = blockIdx.x * blockDim.x + threadIdx.x;
    if (e < E) {
        int s = g_eidx[e];
        int d = g_eidx[E + e];
        if ((unsigned)d < (unsigned)N && (unsigned)s < (unsigned)N) {
            int pos = atomicAdd(&g_cursor[d], 1);
            if (pos < E_MAX) g_adj[pos] = s;
        }
    }
}

// ============================================================
// 3) GATv2 attention + aggregation: HALF-WARP per node.
//    16 lanes own 4 dims each (float4); shfl width 16 with per-half
//    masks; one warp streams 2 nodes' edges concurrently.
// ============================================================
__global__ void agg_kernel(const float* __restrict__ att,
                           const float* __restrict__ gbias, int N) {
    const int gthread = blockIdx.x * blockDim.x + threadIdx.x;
    const int node = gthread >> 4;          // one half-warp per node
    const int lane = threadIdx.x & 15;      // lane within half-warp
    if (node >= N) return;
    const int i = node;
    const unsigned hmask = 0xFFFFu << (threadIdx.x & 16);  // own half's mask

    const float4 xri = *(const float4*)(g_xr + (size_t)i * H_DIM + lane * 4);
    float4 a;
    a.x = att[lane * 4];     a.y = att[lane * 4 + 1];
    a.z = att[lane * 4 + 2]; a.w = att[lane * 4 + 3];
    const float4 xli = *(const float4*)(g_xl + (size_t)i * H_DIM + lane * 4);

    auto partial = [&](float4 x) -> float {
        float v0 = x.x + xri.x, v1 = x.y + xri.y;
        float v2 = x.z + xri.z, v3 = x.w + xri.w;
        v0 = (v0 > 0.f) ? v0 : NEG_SLOPE * v0;
        v1 = (v1 > 0.f) ? v1 : NEG_SLOPE * v1;
        v2 = (v2 > 0.f) ? v2 : NEG_SLOPE * v2;
        v3 = (v3 > 0.f) ? v3 : NEG_SLOPE * v3;
        float p = fmaf(v0, a.x, v1 * a.y);
        p = fmaf(v2, a.z, p);
        p = fmaf(v3, a.w, p);
        return p;
    };

    float m;
    {
        float p = partial(xli);
#pragma unroll
        for (int off = 8; off > 0; off >>= 1)
            p += __shfl_xor_sync(hmask, p, off, 16);
        m = p;
    }
    float d = 1.f;
    float4 acc = xli;

    auto update = [&](float sc, float4 x) {
        if (sc <= m) {
            float w = __expf(sc - m);
            d += w;
            acc.x = fmaf(w, x.x, acc.x);
            acc.y = fmaf(w, x.y, acc.y);
            acc.z = fmaf(w, x.z, acc.z);
            acc.w = fmaf(w, x.w, acc.w);
        } else {
            float scale = __expf(m - sc);
            d = fmaf(d, scale, 1.f);
            acc.x = fmaf(acc.x, scale, x.x);
            acc.y = fmaf(acc.y, scale, x.y);
            acc.z = fmaf(acc.z, scale, x.z);
            acc.w = fmaf(acc.w, scale, x.w);
            m = sc;
        }
    };

    const int s = g_rowptr[i], e = g_rowptr[i + 1];
    for (int b = s; b < e; b += 16) {
        int myj = (b + lane < e) ? g_adj[b + lane] : 0;
        int cnt = min(16, e - b);
        int k = 0;
        for (; k + 1 < cnt; k += 2) {
            int j0 = __shfl_sync(hmask, myj, k, 16);
            int j1 = __shfl_sync(hmask, myj, k + 1, 16);
            float4 x0 = *(const float4*)(g_xl + (size_t)j0 * H_DIM + lane * 4);
            float4 x1 = *(const float4*)(g_xl + (size_t)j1 * H_DIM + lane * 4);
            float p0 = partial(x0);
            float p1 = partial(x1);
#pragma unroll
            for (int off = 8; off > 0; off >>= 1) {
                p0 += __shfl_xor_sync(hmask, p0, off, 16);
                p1 += __shfl_xor_sync(hmask, p1, off, 16);
            }
            update(p0, x0);
            update(p1, x1);
        }
        if (k < cnt) {
            int j0 = __shfl_sync(hmask, myj, k, 16);
            float4 x0 = *(const float4*)(g_xl + (size_t)j0 * H_DIM + lane * 4);
            float p0 = partial(x0);
#pragma unroll
            for (int off = 8; off > 0; off >>= 1)
                p0 += __shfl_xor_sync(hmask, p0, off, 16);
            update(p0, x0);
        }
    }

    const float inv = 1.f / d;
    float gb0 = gbias[lane * 4],     gb1 = gbias[lane * 4 + 1];
    float gb2 = gbias[lane * 4 + 2], gb3 = gbias[lane * 4 + 3];
    float o0 = fmaf(acc.x, inv, gb0);
    float o1 = fmaf(acc.y, inv, gb1);
    float o2 = fmaf(acc.z, inv, gb2);
    float o3 = fmaf(acc.w, inv, gb3);
    o0 = (o0 > 0.f) ? o0 : (__expf(o0) - 1.f);
    o1 = (o1 > 0.f) ? o1 : (__expf(o1) - 1.f);
    o2 = (o2 > 0.f) ? o2 : (__expf(o2) - 1.f);
    o3 = (o3 > 0.f) ? o3 : (__expf(o3) - 1.f);
    float4 r; r.x = o0; r.y = o1; r.z = o2; r.w = o3;
    *(float4*)(g_h + (size_t)i * H_DIM + lane * 4) = r;
}

// ============================================================
// 4) Output GEMM via bf16-split MMA (VERBATIM from R14).
// ============================================================
#define SO_HH   0
#define SO_HL   9216
#define SO_WH   18432
#define SO_WL   36864
#define SO_BIAS 55296
#define OUT2_SMEM 55808

__global__ __launch_bounds__(256) void outgemm_mma_kernel(
        float* __restrict__ out, int N) {
    extern __shared__ char smo[];
    __nv_bfloat16* hh = (__nv_bfloat16*)(smo + SO_HH);
    __nv_bfloat16* hl = (__nv_bfloat16*)(smo + SO_HL);
    float* bis = (float*)(smo + SO_BIAS);

    const int tid = threadIdx.x;
    const int n0 = blockIdx.x * 64;

    {
        const uint4* gwh = (const uint4*)g_wo_hi;
        const uint4* gwl = (const uint4*)g_wo_lo;
        uint4* swh = (uint4*)(smo + SO_WH);
        uint4* swl = (uint4*)(smo + SO_WL);
        for (int i = tid; i < 1152; i += 256) swh[i] = gwh[i];
        for (int i = tid; i < 1152; i += 256) swl[i] = gwl[i];
    }
    for (int i = tid; i < 64 * 32; i += 256) {
        int n = i >> 5, q = i & 31;
        int node = n0 + n;
        float2 v = make_float2(0.f, 0.f);
        if (node < N) v = *(const float2*)(g_h + (size_t)node * H_DIM + q * 2);
        __nv_bfloat16 h0 = __float2bfloat16(v.x);
        __nv_bfloat16 h1 = __float2bfloat16(v.y);
        hh[n * KPAD2 + q * 2]     = h0;
        hh[n * KPAD2 + q * 2 + 1] = h1;
        hl[n * KPAD2 + q * 2]     = __float2bfloat16(v.x - __bfloat162float(h0));
        hl[n * KPAD2 + q * 2 + 1] = __float2bfloat16(v.y - __bfloat162float(h1));
    }
    for (int i = tid; i < 64 * 8; i += 256) {
        int n = i >> 3, k = 64 + (i & 7);
        hh[n * KPAD2 + k] = __float2bfloat16(0.f);
        hl[n * KPAD2 + k] = __float2bfloat16(0.f);
    }
    if (tid < 128) bis[tid] = g_wob[tid];
    __syncthreads();

    const int warp = tid >> 5, lane = tid & 31;
    const int mbase = (warp & 3) * 16;
    const int nwb   = (warp >> 2) * 64;

    float acc[8][4];
#pragma unroll
    for (int t = 0; t < 8; t++)
#pragma unroll
        for (int q = 0; q < 4; q++) acc[t][q] = 0.f;

    const uint32_t sb = smem_u32(smo);
    const uint32_t hh_a = sb + SO_HH, hl_a = sb + SO_HL;
    const uint32_t wh_a = sb + SO_WH, wl_a = sb + SO_WL;

    const int tr = lane & 7, tg = lane >> 3;
    const uint32_t aoff =
        ((uint32_t)((mbase + tr + (tg & 1) * 8) * KPAD2 + ((tg >> 1) * 8))) * 2u;
    uint32_t boff[4];
#pragma unroll
    for (int ng = 0; ng < 4; ng++)
        boff[ng] = ((uint32_t)((nwb + ng * 16 + tr + (tg >> 1) * 8) * KPAD2
                               + ((tg & 1) * 8))) * 2u;

#pragma unroll
    for (int kc = 0; kc < 4; kc++) {
        const uint32_t kb = (uint32_t)kc * 32u;
        uint32_t ah0, ah1, ah2, ah3, al0, al1, al2, al3;
        ldsm_x4(ah0, ah1, ah2, ah3, hh_a + aoff + kb);
        ldsm_x4(al0, al1, al2, al3, hl_a + aoff + kb);
#pragma unroll
        for (int ng = 0; ng < 4; ng++) {
            uint32_t bh0, bh1, bh2, bh3, bl0_, bl1_, bl2_, bl3_;
            ldsm_x4(bh0, bh1, bh2, bh3, wh_a + boff[ng] + kb);
            ldsm_x4(bl0_, bl1_, bl2_, bl3_, wl_a + boff[ng] + kb);
            float* d0 = acc[ng * 2 + 0];
            float* d1 = acc[ng * 2 + 1];
            mma16816(d0[0], d0[1], d0[2], d0[3], ah0, ah1, ah2, ah3, bh0, bh1);
            mma16816(d1[0], d1[1], d1[2], d1[3], ah0, ah1, ah2, ah3, bh2, bh3);
            mma16816(d0[0], d0[1], d0[2], d0[3], ah0, ah1, ah2, ah3, bl0_, bl1_);
            mma16816(d1[0], d1[1], d1[2], d1[3], ah0, ah1, ah2, ah3, bl2_, bl3_);
            mma16816(d0[0], d0[1], d0[2], d0[3], al0, al1, al2, al3, bh0, bh1);
            mma16816(d1[0], d1[1], d1[2], d1[3], al0, al1, al2, al3, bh2, bh3);
        }
    }

    const int r = lane >> 2;
    const int cq = (lane & 3) * 2;
    const int mr0 = mbase + r, mr1 = mbase + r + 8;
    const int node0 = n0 + mr0, node1 = n0 + mr1;
#pragma unroll
    for (int nt = 0; nt < 8; nt++) {
        int f = nwb + nt * 8 + cq;
        float b0 = bis[f], b1 = bis[f + 1];
        if (node0 < N) {
            out[(size_t)node0 * F_DIM + f]     = acc[nt][0] + b0;
            out[(size_t)node0 * F_DIM + f + 1] = acc[nt][1] + b1;
        }
        if (node1 < N) {
            out[(size_t)node1 * F_DIM + f]     = acc[nt][2] + b0;
            out[(size_t)node1 * F_DIM + f + 1] = acc[nt][3] + b1;
        }
    }
}

// ============================================================
// 5) dispersion tail: softplus
// ============================================================
__global__ void disp_kernel(const float* __restrict__ disp, float* __restrict__ out) {
    int t = threadIdx.x;
    if (t < F_DIM) {
        float x = disp[t];
        out[t] = fmaxf(x, 0.f) + log1pf(__expf(-fabsf(x)));
    }
}

// ============================================================
// Stream/event singletons (lazy, created on the un-captured
// correctness call; reused inside capture via fork-join).
// ============================================================
static cudaStream_t g_s2 = 0;
static cudaEvent_t  g_evF = 0, g_evJ = 0;

extern "C" void kernel_launch(void* const* d_in, const int* in_sizes, int n_in,
                              void* d_out, int out_size) {
    const float*     xf   = (const float*)d_in[0];
    const float*     xb   = (const float*)d_in[1];
    const void*      ei   = d_in[2];
    const float*     Wl   = (const float*)d_in[3];
    const float*     bl   = (const float*)d_in[4];
    const float*     Wr   = (const float*)d_in[5];
    const float*     br   = (const float*)d_in[6];
    const float*     att  = (const float*)d_in[7];
    const float*     gb   = (const float*)d_in[8];
    const float*     Wo   = (const float*)d_in[9];
    const float*     bo   = (const float*)d_in[10];
    const float*     disp = (const float*)d_in[11];

    const int N = in_sizes[0] / F_DIM;
    const int E = in_sizes[2] / 2;
    const int NB = (N + 1023) / 1024;
    float* out = (float*)d_out;

    if (!g_s2) {
        cudaStreamCreateWithFlags(&g_s2, cudaStreamNonBlocking);
        cudaEventCreateWithFlags(&g_evF, cudaEventDisableTiming);
        cudaEventCreateWithFlags(&g_evJ, cudaEventDisableTiming);
        cudaFuncSetAttribute(proj_mma_kernel,
                             cudaFuncAttributeMaxDynamicSharedMemorySize, PROJ2_SMEM);
        cudaFuncSetAttribute(outgemm_mma_kernel,
                             cudaFuncAttributeMaxDynamicSharedMemorySize, OUT2_SMEM);
    }

    // ---- fork: proj chain on s2, CSR chain on default ----
    cudaEventRecord(g_evF, 0);
    cudaStreamWaitEvent(g_s2, g_evF, 0);

    // s2: weight split -> projection MMA
    wconv_kernel<<<(128 * KPAD + 255) / 256, 256, 0, g_s2>>>(Wl, Wr, bl, br, Wo, bo);
    proj_mma_kernel<<<(N + 63) / 64, 256, PROJ2_SMEM, g_s2>>>(xf, xb, N);
    cudaEventRecord(g_evJ, g_s2);

    // default: edge conversion + CSR build
    zero_detect_kernel<<<(N + 255) / 256, 256>>>((const int*)ei, 2 * E, N);
    convert_hist_kernel<<<(2 * E + 255) / 256, 256>>>(ei, E, N);
    scan_block_kernel<<<NB, 1024>>>(N);
    scan_fix_kernel<<<(N + 255) / 256, 256>>>(N, NB);
    scatter_kernel<<<(E + 255) / 256, 256>>>(E, N);

    // ---- join: agg needs proj + CSR ----
    cudaStreamWaitEvent(0, g_evJ, 0);
    agg_kernel<<<(N + 15) / 16, 256>>>(att, gb, N);
    outgemm_mma_kernel<<<(N + 63) / 64, 256, OUT2_SMEM>>>(out, N);
    disp_kernel<<<1, 128>>>(disp, out + (size_t)N * F_DIM);
}